// round 2
// baseline (speedup 1.0000x reference)
#include <cuda_runtime.h>
#include <cstdint>

#define T_STEPS 512
#define N_BATCH 64
#define C_IN    512
#define H_DIM   1024
#define P_DIM   512
#define G4H     4096
#define M_TOTAL (T_STEPS * N_BATCH)   /* 32768 */
#define NBLK    128
#define NTHR    256

// ---------------- scratch (device globals: no runtime allocation allowed) -------------
__device__ float g_pre[(size_t)G4H * M_TOTAL];   // pre^T [g][m], 512 MB
__device__ float g_r[P_DIM * N_BATCH];           // r state, [p][n]
__device__ float g_h[H_DIM * N_BATCH];           // gated h, [h][n]
__device__ unsigned g_count;                     // barrier arrive counter (self-resetting)
__device__ unsigned g_sense;                     // barrier sense (even #flips per launch)

__device__ __forceinline__ float sigmoidf_(float x) {
    return 1.0f / (1.0f + __expf(-x));
}
__device__ __forceinline__ float tanhf_(float x) {
    float e = __expf(-2.0f * fabsf(x));
    float t = (1.0f - e) / (1.0f + e);
    return copysignf(t, x);
}

// Sense-reversal grid barrier. Safe for CUDA-graph replay: g_count self-resets,
// g_sense flips an even number of times per launch (2 * T_STEPS), returning to 0.
__device__ __forceinline__ void grid_barrier(unsigned &sense_local) {
    __threadfence();
    __syncthreads();
    if (threadIdx.x == 0) {
        unsigned s = sense_local ^ 1u;
        unsigned arrived = atomicAdd(&g_count, 1u);
        if (arrived == gridDim.x - 1) {
            atomicExch(&g_count, 0u);
            __threadfence();
            atomicExch(&g_sense, s);
        } else {
            while (atomicAdd(&g_sense, 0u) != s) { }
        }
    }
    __syncthreads();
    sense_local ^= 1u;
}

// ---------------- Kernel 1: pre^T[g][m] = x[m][:] . wx[g][:] + b[g] -------------------
// M=32768 (m = t*64+n), K=512, N=4096.  BM=128, BN=64, BK=16, 256 threads,
// per-thread microtile 8m x 4g (m as 4 interleaved float2 groups for conflict-free LDS
// and coalesced float2 STG to the transposed output).
__global__ __launch_bounds__(NTHR)
void pre_gemm(const float* __restrict__ X, const float* __restrict__ W,
              const float* __restrict__ Bb) {
    __shared__ float sA[16][128];
    __shared__ float sB[16][64];
    const int tid = threadIdx.x;
    const int m0 = blockIdx.x * 128;
    const int g0 = blockIdx.y * 64;
    const int tm = tid & 15;
    const int tg = tid >> 4;

    float acc[4][8];
#pragma unroll
    for (int j = 0; j < 4; j++)
#pragma unroll
        for (int i = 0; i < 8; i++) acc[j][i] = 0.0f;

    for (int k0 = 0; k0 < C_IN; k0 += 16) {
#pragma unroll
        for (int f = tid; f < 512; f += NTHR) {         // A tile: 512 float4
            int ml = f >> 2, kq = (f & 3) * 4;
            float4 v = *(const float4*)(X + (size_t)(m0 + ml) * C_IN + k0 + kq);
            sA[kq + 0][ml] = v.x; sA[kq + 1][ml] = v.y;
            sA[kq + 2][ml] = v.z; sA[kq + 3][ml] = v.w;
        }
        {                                                // B tile: 256 float4
            int gl = tid >> 2, kq = (tid & 3) * 4;
            float4 v = *(const float4*)(W + (size_t)(g0 + gl) * C_IN + k0 + kq);
            sB[kq + 0][gl] = v.x; sB[kq + 1][gl] = v.y;
            sB[kq + 2][gl] = v.z; sB[kq + 3][gl] = v.w;
        }
        __syncthreads();
#pragma unroll
        for (int k = 0; k < 16; k++) {
            float2 a0 = *(const float2*)&sA[k][tm * 2];
            float2 a1 = *(const float2*)&sA[k][tm * 2 + 32];
            float2 a2 = *(const float2*)&sA[k][tm * 2 + 64];
            float2 a3 = *(const float2*)&sA[k][tm * 2 + 96];
            float4 b  = *(const float4*)&sB[k][tg * 4];
            float av[8] = {a0.x, a0.y, a1.x, a1.y, a2.x, a2.y, a3.x, a3.y};
            float bv[4] = {b.x, b.y, b.z, b.w};
#pragma unroll
            for (int j = 0; j < 4; j++)
#pragma unroll
                for (int i = 0; i < 8; i++)
                    acc[j][i] = fmaf(av[i], bv[j], acc[j][i]);
        }
        __syncthreads();
    }
    // epilogue: transposed, bias added, coalesced float2 stores
#pragma unroll
    for (int j = 0; j < 4; j++) {
        int g = g0 + tg * 4 + j;
        float bias = __ldg(Bb + g);
        float* dst = g_pre + (size_t)g * M_TOTAL + m0 + tm * 2;
#pragma unroll
        for (int i = 0; i < 4; i++) {
            float2 v;
            v.x = acc[j][2 * i]     + bias;
            v.y = acc[j][2 * i + 1] + bias;
            *(float2*)(dst + i * 32) = v;
        }
    }
}

// ---------------- Kernel 2: persistent LSTM recurrence --------------------------------
// 128 blocks x 256 threads, all co-resident (208KB smem -> 1 CTA/SM, 128 <= 148 SMs).
// Per block: 8 h-columns (x4 gates = 32 wr rows, persistent in smem) and 4 p-columns
// (wo rows persistent in smem). c-state lives in registers. 2 grid barriers per step.
__global__ __launch_bounds__(NTHR)
void lstm_rec(const float* __restrict__ WR, const float* __restrict__ WO,
              const float* __restrict__ WC, const void* __restrict__ Lraw,
              float* __restrict__ out) {
    extern __shared__ float smem[];
    float* s_r  = smem;                   // 32768 floats: r[k][n] / h-chunk[k][n]
    float* s_w  = smem + 32768;           // 16384 floats: 32 wr rows
    float* s_wo = smem + 32768 + 16384;   // 4096  floats: 4 wo rows

    const int tid = threadIdx.x;
    const int blk = blockIdx.x;

    // persistent weights (constant across all 512 steps)
    for (int idx = tid; idx < 32 * 512; idx += NTHR) {
        int lg = idx >> 9, k = idx & 511;
        int gate = lg >> 3, hl = lg & 7;
        s_w[idx] = WR[(size_t)(gate * H_DIM + blk * 8 + hl) * P_DIM + k];
    }
    for (int idx = tid; idx < 4 * 1024; idx += NTHR) {
        int pl = idx >> 10, k = idx & 1023;
        s_wo[idx] = WO[(size_t)(blk * 4 + pl) * H_DIM + k];
    }

    const int warp = tid >> 5, lane = tid & 31;
    const int n   = (warp >> 2) * 32 + lane;   // batch index owned by this thread
    const int hl2 = (warp & 3) * 2;            // local h pair
    const int h0  = blk * 8 + hl2;             // global h column (this thread owns h0,h0+1)
    const int pl3 = warp & 3;
    const int p3  = blk * 4 + pl3;             // global p column for phase 3

    const float wci0 = WC[h0],             wci1 = WC[h0 + 1];
    const float wcf0 = WC[H_DIM + h0],     wcf1 = WC[H_DIM + h0 + 1];
    const float wco0 = WC[2 * H_DIM + h0], wco1 = WC[2 * H_DIM + h0 + 1];

    // lengths dtype detection (jax may silently downcast int64->int32):
    // if the data is int32 pairs, the first int64 read is >= 2^32 (both values >= 1).
    long long first = *(const long long*)Lraw;
    long long len_n;
    if (first >= 1 && first <= (long long)T_STEPS)
        len_n = ((const long long*)Lraw)[n];
    else
        len_n = (long long)((const int*)Lraw)[n];

    float c0 = 0.0f, c1 = 0.0f;          // cell state: registers, all 512 steps
    unsigned sense = 0;

    const float* wrow[8];
#pragma unroll
    for (int q = 0; q < 8; q++) {
        int gate = q >> 1, j = q & 1;
        wrow[q] = s_w + (gate * 8 + hl2 + j) * 512;
    }
    const float* worow = s_wo + pl3 * 1024;

    __syncthreads();

    for (int t = 0; t < T_STEPS; t++) {
        // ---- load r into smem ([p][n] layout, straight copy) ----
        if (t > 0) {
            for (int idx = tid * 4; idx < P_DIM * N_BATCH; idx += NTHR * 4) {
                float4 v = __ldcg((const float4*)(g_r + idx));
                *(float4*)(s_r + idx) = v;
            }
        }
        __syncthreads();

        // ---- phase 1: g = pre[t] + r @ wr^T for this thread's 8 gate columns ----
        const int m = t * N_BATCH + n;
        float pv[8];
#pragma unroll
        for (int q = 0; q < 8; q++) {
            int gate = q >> 1, j = q & 1;
            pv[q] = __ldg(g_pre + (size_t)(gate * H_DIM + h0 + j) * M_TOTAL + m);
        }
        float acc[8];
#pragma unroll
        for (int q = 0; q < 8; q++) acc[q] = 0.0f;

        if (t > 0) {
#pragma unroll 2
            for (int k = 0; k < P_DIM; k += 4) {
                float r0 = s_r[(k    ) * 64 + n];
                float r1 = s_r[(k + 1) * 64 + n];
                float r2 = s_r[(k + 2) * 64 + n];
                float r3 = s_r[(k + 3) * 64 + n];
#pragma unroll
                for (int q = 0; q < 8; q++) {
                    float4 w = *(const float4*)(wrow[q] + k);
                    acc[q] = fmaf(r0, w.x, acc[q]);
                    acc[q] = fmaf(r1, w.y, acc[q]);
                    acc[q] = fmaf(r2, w.z, acc[q]);
                    acc[q] = fmaf(r3, w.w, acc[q]);
                }
            }
        }
#pragma unroll
        for (int q = 0; q < 8; q++) acc[q] += pv[q];

        // ---- phase 2: gates (all local: this thread owns i,f,o,cand for h0,h0+1) ----
        {
            float in0 = sigmoidf_(acc[0] + wci0 * c0);
            float fg0 = sigmoidf_(acc[2] + wcf0 * c0);
            float cc0 = fg0 * c0 + in0 * tanhf_(acc[6]);
            float og0 = sigmoidf_(acc[4] + wco0 * cc0);
            float hv0 = og0 * tanhf_(cc0);
            c0 = cc0;
            float in1 = sigmoidf_(acc[1] + wci1 * c1);
            float fg1 = sigmoidf_(acc[3] + wcf1 * c1);
            float cc1 = fg1 * c1 + in1 * tanhf_(acc[7]);
            float og1 = sigmoidf_(acc[5] + wco1 * cc1);
            float hv1 = og1 * tanhf_(cc1);
            c1 = cc1;
            g_h[(h0    ) * 64 + n] = hv0;
            g_h[(h0 + 1) * 64 + n] = hv1;
        }

        grid_barrier(sense);   // h complete chip-wide

        // ---- phase 3: r_new[n][p3] = h . wo[p3], h staged through smem in 4 chunks ----
        float racc = 0.0f;
#pragma unroll 1
        for (int ch = 0; ch < 4; ch++) {
            __syncthreads();
            const float* src = g_h + ch * 16384;
            for (int idx = tid * 4; idx < 16384; idx += NTHR * 4) {
                float4 v = __ldcg((const float4*)(src + idx));
                *(float4*)(s_r + idx) = v;
            }
            __syncthreads();
            const float* wk = worow + ch * 256;
#pragma unroll 4
            for (int k = 0; k < 256; k += 4) {
                float4 w = *(const float4*)(wk + k);
                racc = fmaf(s_r[(k    ) * 64 + n], w.x, racc);
                racc = fmaf(s_r[(k + 1) * 64 + n], w.y, racc);
                racc = fmaf(s_r[(k + 2) * 64 + n], w.z, racc);
                racc = fmaf(s_r[(k + 3) * 64 + n], w.w, racc);
            }
        }
        g_r[p3 * 64 + n] = racc;
        out[(size_t)(t * N_BATCH + n) * P_DIM + p3] = (t < len_n) ? racc : 0.0f;

        grid_barrier(sense);   // r complete chip-wide
    }
}

// ---------------- launch --------------------------------------------------------------
extern "C" void kernel_launch(void* const* d_in, const int* in_sizes, int n_in,
                              void* d_out, int out_size) {
    const float* x = nullptr;
    const void*  lengths = nullptr;
    const float* wx_w = nullptr;
    const float* wx_b = nullptr;
    const float* wr_w = nullptr;
    const float* wo_w = nullptr;
    const float* wc = nullptr;

    // map inputs by element count (wx_w and wr_w share a size: order disambiguates)
    for (int i = 0; i < n_in; i++) {
        int s = in_sizes[i];
        if      (s == T_STEPS * N_BATCH * C_IN) x = (const float*)d_in[i];
        else if (s == N_BATCH)                  lengths = d_in[i];
        else if (s == 4 * H_DIM * C_IN) {
            if (!wx_w) wx_w = (const float*)d_in[i];
            else       wr_w = (const float*)d_in[i];
        }
        else if (s == 4 * H_DIM)                wx_b = (const float*)d_in[i];
        else if (s == P_DIM * H_DIM)            wo_w = (const float*)d_in[i];
        else if (s == 3 * H_DIM)                wc = (const float*)d_in[i];
    }

    const int smem_bytes = (32768 + 16384 + 4096) * 4;   // 208 KB
    cudaFuncSetAttribute(lstm_rec, cudaFuncAttributeMaxDynamicSharedMemorySize,
                         smem_bytes);

    dim3 grid1(M_TOTAL / 128, G4H / 64);
    pre_gemm<<<grid1, NTHR>>>(x, wx_w, wx_b);
    lstm_rec<<<NBLK, NTHR, smem_bytes>>>(wr_w, wo_w, wc, lengths, (float*)d_out);
}

// round 3
// speedup vs baseline: 1.1503x; 1.1503x over previous
#include <cuda_runtime.h>
#include <cstdint>

#define T_STEPS 512
#define N_BATCH 64
#define C_IN    512
#define H_DIM   1024
#define P_DIM   512
#define G4H     4096
#define M_TOTAL (T_STEPS * N_BATCH)   /* 32768 */
#define NBLK    128
#define NTHR    256

typedef unsigned long long u64t;

// ---------------- scratch (device globals: no runtime allocation allowed) -------------
__device__ float g_pre[(size_t)G4H * M_TOTAL];   // pre^T [g][m], 512 MB
__device__ float g_r[P_DIM * N_BATCH];           // r state, [p][n]
__device__ float g_h[H_DIM * N_BATCH];           // gated h, [h][n]
__device__ unsigned g_count;                     // barrier arrive counter (self-resetting)
__device__ unsigned g_sense;                     // barrier sense (even #flips per launch)

// ---------------- f32x2 packed-FMA helpers (sm_100+) ----------------------------------
__device__ __forceinline__ u64t pk2(float lo, float hi) {
    u64t r; asm("mov.b64 %0, {%1, %2};" : "=l"(r) : "f"(lo), "f"(hi)); return r;
}
__device__ __forceinline__ void unpk2(u64t v, float &lo, float &hi) {
    asm("mov.b64 {%0, %1}, %2;" : "=f"(lo), "=f"(hi) : "l"(v));
}
__device__ __forceinline__ void fma2(u64t &d, u64t a, u64t b) {
    asm("fma.rn.f32x2 %0, %1, %2, %0;" : "+l"(d) : "l"(a), "l"(b));
}
__device__ __forceinline__ u64t add2(u64t a, u64t b) {
    u64t r; asm("add.rn.f32x2 %0, %1, %2;" : "=l"(r) : "l"(a), "l"(b)); return r;
}

// ---------------- cp.async helpers ----------------------------------------------------
__device__ __forceinline__ void cpa16(const float* smem_dst, const float* gsrc) {
    uint32_t d = (uint32_t)__cvta_generic_to_shared(smem_dst);
    asm volatile("cp.async.cg.shared.global [%0], [%1], 16;" :: "r"(d), "l"(gsrc));
}
#define CP_COMMIT() asm volatile("cp.async.commit_group;" ::: "memory")
#define CP_WAIT0()  asm volatile("cp.async.wait_group 0;" ::: "memory")
#define CP_WAIT1()  asm volatile("cp.async.wait_group 1;" ::: "memory")

__device__ __forceinline__ float sigmoidf_(float x) {
    return 1.0f / (1.0f + __expf(-x));
}
__device__ __forceinline__ float tanhf_(float x) {
    float e = __expf(-2.0f * fabsf(x));
    float t = (1.0f - e) / (1.0f + e);
    return copysignf(t, x);
}

// Sense-reversal grid barrier: release-atomic arrive, acquire-load poll (no atomic
// polling storm). Graph-replay safe: g_count self-resets, g_sense flips an even
// number of times per launch (2*T_STEPS) returning to 0.
__device__ __forceinline__ void grid_barrier(unsigned &sense_local) {
    __threadfence();
    __syncthreads();
    if (threadIdx.x == 0) {
        unsigned s = sense_local ^ 1u;
        unsigned prev;
        asm volatile("atom.release.gpu.global.add.u32 %0, [%1], %2;"
                     : "=r"(prev) : "l"(&g_count), "r"(1u) : "memory");
        if (prev == gridDim.x - 1) {
            g_count = 0;   // ordered before the release-store below
            asm volatile("st.release.gpu.global.u32 [%0], %1;"
                         :: "l"(&g_sense), "r"(s) : "memory");
        } else {
            unsigned v;
            do {
                asm volatile("ld.acquire.gpu.global.u32 %0, [%1];"
                             : "=r"(v) : "l"(&g_sense) : "memory");
            } while (v != s);
        }
    }
    __syncthreads();
    sense_local ^= 1u;
}

// ---------------- Kernel 1: pre^T[g][m] = x[m][:] . wx[g][:] + b[g] -------------------
// Same structure as round-1 (90% of scalar-FFMA roofline) but inner loop in packed
// f32x2: a-operands are m-pairs read directly as LDS.64 from the [k][m] tile,
// b-operands duplicated per gate; 16 FFMA2 per k instead of 32 FFMA.
__global__ __launch_bounds__(NTHR)
void pre_gemm(const float* __restrict__ X, const float* __restrict__ W,
              const float* __restrict__ Bb) {
    __shared__ float sA[16][128];
    __shared__ float sB[16][64];
    const int tid = threadIdx.x;
    const int m0 = blockIdx.x * 128;
    const int g0 = blockIdx.y * 64;
    const int tm = tid & 15;
    const int tg = tid >> 4;

    u64t acc2[4][4];
#pragma unroll
    for (int j = 0; j < 4; j++)
#pragma unroll
        for (int i = 0; i < 4; i++) acc2[j][i] = 0ull;

    for (int k0 = 0; k0 < C_IN; k0 += 16) {
#pragma unroll
        for (int f = tid; f < 512; f += NTHR) {         // A tile: 512 float4
            int ml = f >> 2, kq = (f & 3) * 4;
            float4 v = *(const float4*)(X + (size_t)(m0 + ml) * C_IN + k0 + kq);
            sA[kq + 0][ml] = v.x; sA[kq + 1][ml] = v.y;
            sA[kq + 2][ml] = v.z; sA[kq + 3][ml] = v.w;
        }
        {                                                // B tile: 256 float4
            int gl = tid >> 2, kq = (tid & 3) * 4;
            float4 v = *(const float4*)(W + (size_t)(g0 + gl) * C_IN + k0 + kq);
            sB[kq + 0][gl] = v.x; sB[kq + 1][gl] = v.y;
            sB[kq + 2][gl] = v.z; sB[kq + 3][gl] = v.w;
        }
        __syncthreads();
#pragma unroll
        for (int k = 0; k < 16; k++) {
            u64t a0 = *(const u64t*)&sA[k][tm * 2];
            u64t a1 = *(const u64t*)&sA[k][tm * 2 + 32];
            u64t a2 = *(const u64t*)&sA[k][tm * 2 + 64];
            u64t a3 = *(const u64t*)&sA[k][tm * 2 + 96];
            float4 b = *(const float4*)&sB[k][tg * 4];
            u64t b0 = pk2(b.x, b.x), b1 = pk2(b.y, b.y);
            u64t b2 = pk2(b.z, b.z), b3 = pk2(b.w, b.w);
            fma2(acc2[0][0], a0, b0); fma2(acc2[0][1], a1, b0);
            fma2(acc2[0][2], a2, b0); fma2(acc2[0][3], a3, b0);
            fma2(acc2[1][0], a0, b1); fma2(acc2[1][1], a1, b1);
            fma2(acc2[1][2], a2, b1); fma2(acc2[1][3], a3, b1);
            fma2(acc2[2][0], a0, b2); fma2(acc2[2][1], a1, b2);
            fma2(acc2[2][2], a2, b2); fma2(acc2[2][3], a3, b2);
            fma2(acc2[3][0], a0, b3); fma2(acc2[3][1], a1, b3);
            fma2(acc2[3][2], a2, b3); fma2(acc2[3][3], a3, b3);
        }
        __syncthreads();
    }
    // epilogue: transposed, bias added, 8B stores
#pragma unroll
    for (int j = 0; j < 4; j++) {
        int g = g0 + tg * 4 + j;
        float bias = __ldg(Bb + g);
        u64t bias2 = pk2(bias, bias);
        float* dst = g_pre + (size_t)g * M_TOTAL + m0 + tm * 2;
#pragma unroll
        for (int i = 0; i < 4; i++) {
            *(u64t*)(dst + i * 32) = add2(acc2[j][i], bias2);
        }
    }
}

// ---------------- Kernel 2: persistent LSTM recurrence --------------------------------
// 128 blocks x 256 threads, all co-resident. Per block: 8 h-columns (32 wr rows,
// interleaved [k][col] for one-LDS.128-per-2-gates f32x2 operands) and 4 p-columns.
// c-state in registers. r/h staged through smem via pipelined cp.async.cg.
__global__ __launch_bounds__(NTHR)
void lstm_rec(const float* __restrict__ WR, const float* __restrict__ WO,
              const float* __restrict__ WC, const void* __restrict__ Lraw,
              float* __restrict__ out) {
    extern __shared__ float smem[];
    float* s_r   = smem;                    // 32768 f: r[k][n] / 2 x h-chunk[k][n]
    float* s_w   = smem + 32768;            // 16384 f: wr interleaved [k][32]
    float* s_wo4 = smem + 32768 + 16384;    // 4096  f: wo interleaved [k][4]
    float* s_red = smem + 32768 + 16384 + 4096; // 1024 f: phase-3 reduction

    const int tid = threadIdx.x;
    const int blk = blockIdx.x;

    // --- persistent weights, interleaved ---
    // s_w[k*32 + p4*8 + gate*2 + j] = WR[(gate*H + blk*8 + p4*2 + j)*P + k]
    for (int idx = tid; idx < 32 * 512; idx += NTHR) {
        int row = idx >> 9, k = idx & 511;
        int gate = row >> 3, hl = row & 7;
        int col = (hl >> 1) * 8 + gate * 2 + (hl & 1);
        s_w[k * 32 + col] = WR[(size_t)(gate * H_DIM + blk * 8 + hl) * P_DIM + k];
    }
    // s_wo4[k*4 + pl] = WO[(blk*4+pl)*H + k]
    for (int idx = tid; idx < 4 * 1024; idx += NTHR) {
        int pl = idx >> 10, k = idx & 1023;
        s_wo4[k * 4 + pl] = WO[(size_t)(blk * 4 + pl) * H_DIM + k];
    }

    const int warp = tid >> 5, lane = tid & 31;
    // phase-1 mapping
    const int n  = (warp >> 2) * 32 + lane;    // batch index
    const int p4 = warp & 3;                   // h-pair within block
    const int h0 = blk * 8 + p4 * 2;           // this thread owns h0, h0+1
    // phase-3 mapping
    const int kq = tid >> 6;                   // k-quadrant 0..3 (also final p index)
    const int n3 = tid & 63;
    const int p3 = blk * 4 + kq;

    const float wci0 = WC[h0],             wci1 = WC[h0 + 1];
    const float wcf0 = WC[H_DIM + h0],     wcf1 = WC[H_DIM + h0 + 1];
    const float wco0 = WC[2 * H_DIM + h0], wco1 = WC[2 * H_DIM + h0 + 1];

    // lengths dtype detection (int64 vs int32): int32 pair read as int64 is >= 2^32
    long long first = *(const long long*)Lraw;
    long long len3;
    if (first >= 1 && first <= (long long)T_STEPS)
        len3 = ((const long long*)Lraw)[n3];
    else
        len3 = (long long)((const int*)Lraw)[n3];

    float c0 = 0.0f, c1 = 0.0f;
    unsigned sense = 0;

    const float* wbase  = s_w + p4 * 8;
    float* buf0 = s_r;
    float* buf1 = s_r + 16384;

    __syncthreads();

    for (int t = 0; t < T_STEPS; t++) {
        // ---- stage r (2 pipelined cp.async groups) ----
        if (t > 0) {
            for (int i = tid * 4; i < 16384; i += NTHR * 4) cpa16(s_r + i, g_r + i);
            CP_COMMIT();
            for (int i = 16384 + tid * 4; i < 32768; i += NTHR * 4) cpa16(s_r + i, g_r + i);
            CP_COMMIT();
        }

        // ---- pre[t] loads (overlap with cp.async) ----
        const int m = t * N_BATCH + n;
        float pvv[8];
#pragma unroll
        for (int g = 0; g < 4; g++)
#pragma unroll
            for (int j = 0; j < 2; j++)
                pvv[g * 2 + j] =
                    __ldg(g_pre + (size_t)(g * H_DIM + h0 + j) * M_TOTAL + m);

        u64t acc[4];
#pragma unroll
        for (int g = 0; g < 4; g++) acc[g] = pk2(pvv[g * 2], pvv[g * 2 + 1]);

        // ---- phase 1: acc += r . wr (f32x2, gate pairs) ----
        if (t > 0) {
            CP_WAIT1();
            __syncthreads();
#pragma unroll 4
            for (int k = 0; k < 256; k++) {
                float rv = s_r[k * 64 + n];
                u64t r2 = pk2(rv, rv);
                ulonglong2 wa = *(const ulonglong2*)(wbase + (size_t)k * 32);
                ulonglong2 wb = *(const ulonglong2*)(wbase + (size_t)k * 32 + 4);
                fma2(acc[0], r2, wa.x);
                fma2(acc[1], r2, wa.y);
                fma2(acc[2], r2, wb.x);
                fma2(acc[3], r2, wb.y);
            }
            CP_WAIT0();
            __syncthreads();
#pragma unroll 4
            for (int k = 256; k < 512; k++) {
                float rv = s_r[k * 64 + n];
                u64t r2 = pk2(rv, rv);
                ulonglong2 wa = *(const ulonglong2*)(wbase + (size_t)k * 32);
                ulonglong2 wb = *(const ulonglong2*)(wbase + (size_t)k * 32 + 4);
                fma2(acc[0], r2, wa.x);
                fma2(acc[1], r2, wa.y);
                fma2(acc[2], r2, wb.x);
                fma2(acc[3], r2, wb.y);
            }
        }

        // ---- phase 2: gates (thread-local), h -> g_h ----
        {
            float i0, i1, f0, f1, o0, o1, co0, co1;
            unpk2(acc[0], i0, i1); unpk2(acc[1], f0, f1);
            unpk2(acc[2], o0, o1); unpk2(acc[3], co0, co1);

            float in0 = sigmoidf_(i0 + wci0 * c0);
            float fg0 = sigmoidf_(f0 + wcf0 * c0);
            float cc0 = fg0 * c0 + in0 * tanhf_(co0);
            float og0 = sigmoidf_(o0 + wco0 * cc0);
            float hv0 = og0 * tanhf_(cc0);
            c0 = cc0;
            float in1 = sigmoidf_(i1 + wci1 * c1);
            float fg1 = sigmoidf_(f1 + wcf1 * c1);
            float cc1 = fg1 * c1 + in1 * tanhf_(co1);
            float og1 = sigmoidf_(o1 + wco1 * cc1);
            float hv1 = og1 * tanhf_(cc1);
            c1 = cc1;
            __stcg(&g_h[(h0)     * 64 + n], hv0);
            __stcg(&g_h[(h0 + 1) * 64 + n], hv1);
        }

        grid_barrier(sense);   // h complete chip-wide

        // ---- phase 3: r_new[n][p] = h . wo[p], pipelined h chunks + 4-way k-split ----
        // prefetch chunks 0,1
        for (int i = tid * 4; i < 16384; i += NTHR * 4) cpa16(buf0 + i, g_h + i);
        CP_COMMIT();
        for (int i = tid * 4; i < 16384; i += NTHR * 4) cpa16(buf1 + i, g_h + 16384 + i);
        CP_COMMIT();

        u64t a01 = 0ull, a23 = 0ull;
#pragma unroll 1
        for (int ch = 0; ch < 4; ch++) {
            if (ch < 3) CP_WAIT1(); else CP_WAIT0();
            __syncthreads();
            const float* buf = (ch & 1) ? buf1 : buf0;
            const float* wo  = s_wo4 + (size_t)(ch * 256 + kq * 64) * 4;
            const float* hb  = buf + kq * 64 * 64 + n3;
#pragma unroll 8
            for (int kk = 0; kk < 64; kk++) {
                float hv = hb[kk * 64];
                u64t h2 = pk2(hv, hv);
                ulonglong2 w4 = *(const ulonglong2*)(wo + kk * 4);
                fma2(a01, h2, w4.x);
                fma2(a23, h2, w4.y);
            }
            __syncthreads();
            if (ch < 2) {   // prefetch chunk ch+2 into the buffer just freed
                float* db = (ch & 1) ? buf1 : buf0;
                const float* src = g_h + (ch + 2) * 16384;
                for (int i = tid * 4; i < 16384; i += NTHR * 4) cpa16(db + i, src + i);
                CP_COMMIT();
            }
        }

        // reduction over the 4 k-quadrants: s_red[p][kq][n]
        {
            float q0, q1, q2, q3;
            unpk2(a01, q0, q1); unpk2(a23, q2, q3);
            s_red[0 * 256 + kq * 64 + n3] = q0;
            s_red[1 * 256 + kq * 64 + n3] = q1;
            s_red[2 * 256 + kq * 64 + n3] = q2;
            s_red[3 * 256 + kq * 64 + n3] = q3;
        }
        __syncthreads();
        {
            const float* rp = s_red + kq * 256 + n3;
            float v = rp[0] + rp[64] + rp[128] + rp[192];
            __stcg(&g_r[p3 * 64 + n3], v);
            out[(size_t)(t * N_BATCH + n3) * P_DIM + p3] = (t < len3) ? v : 0.0f;
        }

        grid_barrier(sense);   // r complete chip-wide
    }
}

// ---------------- launch --------------------------------------------------------------
extern "C" void kernel_launch(void* const* d_in, const int* in_sizes, int n_in,
                              void* d_out, int out_size) {
    const float* x = nullptr;
    const void*  lengths = nullptr;
    const float* wx_w = nullptr;
    const float* wx_b = nullptr;
    const float* wr_w = nullptr;
    const float* wo_w = nullptr;
    const float* wc = nullptr;

    for (int i = 0; i < n_in; i++) {
        int s = in_sizes[i];
        if      (s == T_STEPS * N_BATCH * C_IN) x = (const float*)d_in[i];
        else if (s == N_BATCH)                  lengths = d_in[i];
        else if (s == 4 * H_DIM * C_IN) {
            if (!wx_w) wx_w = (const float*)d_in[i];
            else       wr_w = (const float*)d_in[i];
        }
        else if (s == 4 * H_DIM)                wx_b = (const float*)d_in[i];
        else if (s == P_DIM * H_DIM)            wo_w = (const float*)d_in[i];
        else if (s == 3 * H_DIM)                wc = (const float*)d_in[i];
    }

    const int smem_bytes = (32768 + 16384 + 4096 + 1024) * 4;   // 212 KB + red
    cudaFuncSetAttribute(lstm_rec, cudaFuncAttributeMaxDynamicSharedMemorySize,
                         smem_bytes);

    dim3 grid1(M_TOTAL / 128, G4H / 64);
    pre_gemm<<<grid1, NTHR>>>(x, wx_w, wx_b);
    lstm_rec<<<NBLK, NTHR, smem_bytes>>>(wr_w, wo_w, wc, lengths, (float*)d_out);
}

// round 4
// speedup vs baseline: 1.2943x; 1.1253x over previous
#include <cuda_runtime.h>
#include <cstdint>

#define T_STEPS 512
#define N_BATCH 64
#define C_IN    512
#define H_DIM   1024
#define P_DIM   512
#define G4H     4096
#define M_TOTAL (T_STEPS * N_BATCH)   /* 32768 */
#define NBLK    128
#define NTHR    512                   /* recurrence kernel threads */
#define GTHR    256                   /* pre_gemm threads */

typedef unsigned long long u64t;

// ---------------- scratch (device globals: no runtime allocation allowed) -------------
__device__ float g_pre[(size_t)G4H * M_TOTAL];   // pre^T [g][m], 512 MB
__device__ float g_r[P_DIM * N_BATCH];           // r state, [p][n]
__device__ float g_h[H_DIM * N_BATCH];           // gated h, [h][n]
__device__ unsigned g_count;                     // barrier arrive counter (self-resetting)
__device__ unsigned g_sense;                     // barrier sense (even #flips per launch)

// ---------------- f32x2 packed-FMA helpers (sm_100+) ----------------------------------
__device__ __forceinline__ u64t pk2(float lo, float hi) {
    u64t r; asm("mov.b64 %0, {%1, %2};" : "=l"(r) : "f"(lo), "f"(hi)); return r;
}
__device__ __forceinline__ void unpk2(u64t v, float &lo, float &hi) {
    asm("mov.b64 {%0, %1}, %2;" : "=f"(lo), "=f"(hi) : "l"(v));
}
__device__ __forceinline__ void fma2(u64t &d, u64t a, u64t b) {
    asm("fma.rn.f32x2 %0, %1, %2, %0;" : "+l"(d) : "l"(a), "l"(b));
}
__device__ __forceinline__ u64t add2(u64t a, u64t b) {
    u64t r; asm("add.rn.f32x2 %0, %1, %2;" : "=l"(r) : "l"(a), "l"(b)); return r;
}

// ---------------- cp.async helpers ----------------------------------------------------
__device__ __forceinline__ void cpa16(const float* smem_dst, const float* gsrc) {
    uint32_t d = (uint32_t)__cvta_generic_to_shared(smem_dst);
    asm volatile("cp.async.cg.shared.global [%0], [%1], 16;" :: "r"(d), "l"(gsrc));
}
#define CP_COMMIT() asm volatile("cp.async.commit_group;" ::: "memory")
#define CP_WAIT0()  asm volatile("cp.async.wait_group 0;" ::: "memory")
#define CP_WAIT1()  asm volatile("cp.async.wait_group 1;" ::: "memory")

__device__ __forceinline__ float sigmoidf_(float x) {
    return 1.0f / (1.0f + __expf(-x));
}
__device__ __forceinline__ float tanhf_(float x) {
    float e = __expf(-2.0f * fabsf(x));
    float t = (1.0f - e) / (1.0f + e);
    return copysignf(t, x);
}

// Sense-reversal grid barrier. No __threadfence (no L1 flush needed: all cross-CTA
// traffic uses L2-scoped paths: st.cg / cp.async.cg / atomics). acq_rel arrive +
// release publish + acquire poll give the ordering. Graph-replay safe: g_count
// self-resets; g_sense flips an even number of times per launch.
__device__ __forceinline__ void grid_barrier(unsigned &sense_local) {
    __syncthreads();
    if (threadIdx.x == 0) {
        unsigned s = sense_local ^ 1u;
        unsigned prev;
        asm volatile("atom.acq_rel.gpu.global.add.u32 %0, [%1], %2;"
                     : "=r"(prev) : "l"(&g_count), "r"(1u) : "memory");
        if (prev == gridDim.x - 1) {
            g_count = 0;   // ordered before the release-store below
            asm volatile("st.release.gpu.global.u32 [%0], %1;"
                         :: "l"(&g_sense), "r"(s) : "memory");
        } else {
            unsigned v;
            do {
                asm volatile("ld.acquire.gpu.global.u32 %0, [%1];"
                             : "=r"(v) : "l"(&g_sense) : "memory");
            } while (v != s);
        }
    }
    __syncthreads();
    sense_local ^= 1u;
}

// ---------------- Kernel 1: pre^T[g][m] = x[m][:] . wx[g][:] + b[g] -------------------
__global__ __launch_bounds__(GTHR)
void pre_gemm(const float* __restrict__ X, const float* __restrict__ W,
              const float* __restrict__ Bb) {
    __shared__ float sA[16][128];
    __shared__ float sB[16][64];
    const int tid = threadIdx.x;
    const int m0 = blockIdx.x * 128;
    const int g0 = blockIdx.y * 64;
    const int tm = tid & 15;
    const int tg = tid >> 4;

    u64t acc2[4][4];
#pragma unroll
    for (int j = 0; j < 4; j++)
#pragma unroll
        for (int i = 0; i < 4; i++) acc2[j][i] = 0ull;

    for (int k0 = 0; k0 < C_IN; k0 += 16) {
#pragma unroll
        for (int f = tid; f < 512; f += GTHR) {         // A tile: 512 float4
            int ml = f >> 2, kq = (f & 3) * 4;
            float4 v = *(const float4*)(X + (size_t)(m0 + ml) * C_IN + k0 + kq);
            sA[kq + 0][ml] = v.x; sA[kq + 1][ml] = v.y;
            sA[kq + 2][ml] = v.z; sA[kq + 3][ml] = v.w;
        }
        {                                                // B tile: 256 float4
            int gl = tid >> 2, kq = (tid & 3) * 4;
            float4 v = *(const float4*)(W + (size_t)(g0 + gl) * C_IN + k0 + kq);
            sB[kq + 0][gl] = v.x; sB[kq + 1][gl] = v.y;
            sB[kq + 2][gl] = v.z; sB[kq + 3][gl] = v.w;
        }
        __syncthreads();
#pragma unroll
        for (int k = 0; k < 16; k++) {
            u64t a0 = *(const u64t*)&sA[k][tm * 2];
            u64t a1 = *(const u64t*)&sA[k][tm * 2 + 32];
            u64t a2 = *(const u64t*)&sA[k][tm * 2 + 64];
            u64t a3 = *(const u64t*)&sA[k][tm * 2 + 96];
            float4 b = *(const float4*)&sB[k][tg * 4];
            u64t b0 = pk2(b.x, b.x), b1 = pk2(b.y, b.y);
            u64t b2 = pk2(b.z, b.z), b3 = pk2(b.w, b.w);
            fma2(acc2[0][0], a0, b0); fma2(acc2[0][1], a1, b0);
            fma2(acc2[0][2], a2, b0); fma2(acc2[0][3], a3, b0);
            fma2(acc2[1][0], a0, b1); fma2(acc2[1][1], a1, b1);
            fma2(acc2[1][2], a2, b1); fma2(acc2[1][3], a3, b1);
            fma2(acc2[2][0], a0, b2); fma2(acc2[2][1], a1, b2);
            fma2(acc2[2][2], a2, b2); fma2(acc2[2][3], a3, b2);
            fma2(acc2[3][0], a0, b3); fma2(acc2[3][1], a1, b3);
            fma2(acc2[3][2], a2, b3); fma2(acc2[3][3], a3, b3);
        }
        __syncthreads();
    }
#pragma unroll
    for (int j = 0; j < 4; j++) {
        int g = g0 + tg * 4 + j;
        float bias = __ldg(Bb + g);
        u64t bias2 = pk2(bias, bias);
        float* dst = g_pre + (size_t)g * M_TOTAL + m0 + tm * 2;
#pragma unroll
        for (int i = 0; i < 4; i++) {
            *(u64t*)(dst + i * 32) = add2(acc2[j][i], bias2);
        }
    }
}

// ---------------- Kernel 2: persistent LSTM recurrence --------------------------------
// 128 blocks x 512 threads (16 warps, 4/SMSP for latency hiding). Phase-1: K split in
// halves across warp groups, smem reduction. Phase-3: K split 8 ways. c in registers.
__global__ __launch_bounds__(NTHR)
void lstm_rec(const float* __restrict__ WR, const float* __restrict__ WO,
              const float* __restrict__ WC, const void* __restrict__ Lraw,
              float* __restrict__ out) {
    extern __shared__ float smem[];
    float* s_r   = smem;                    // 32768 f: r[k][n] / 2 x h-chunk[k][n]
    float* s_w   = smem + 32768;            // 16384 f: wr interleaved [k][32]
    float* s_wo4 = smem + 32768 + 16384;    // 4096  f: wo interleaved [k][4]
    float* s_red = smem + 32768 + 16384 + 4096; // 2048 f (8KB): cross-split reductions

    const int tid = threadIdx.x;
    const int blk = blockIdx.x;

    // --- persistent weights, interleaved ---
    // s_w[k*32 + p4*8 + gate*2 + j] = WR[(gate*H + blk*8 + p4*2 + j)*P + k]
    for (int idx = tid; idx < 32 * 512; idx += NTHR) {
        int row = idx >> 9, k = idx & 511;
        int gate = row >> 3, hl = row & 7;
        int col = (hl >> 1) * 8 + gate * 2 + (hl & 1);
        s_w[k * 32 + col] = WR[(size_t)(gate * H_DIM + blk * 8 + hl) * P_DIM + k];
    }
    // s_wo4[k*4 + pl] = WO[(blk*4+pl)*H + k]
    for (int idx = tid; idx < 4 * 1024; idx += NTHR) {
        int pl = idx >> 10, k = idx & 1023;
        s_wo4[k * 4 + pl] = WO[(size_t)(blk * 4 + pl) * H_DIM + k];
    }

    const int warp = tid >> 5, lane = tid & 31;
    // phase-1 mapping: n from (warp&1, lane), h-pair from (warp>>1)&3, K-half warp>>3
    const int n  = (warp & 1) * 32 + lane;
    const int p4 = (warp >> 1) & 3;
    const int kh = warp >> 3;                  // 0 or 1 (K half)
    const int h0 = blk * 8 + p4 * 2;
    // phase-3 mapping: kslot = K-eighth within chunk; kslot<4 doubles as output p
    const int kslot = tid >> 6;                // 0..7
    const int n3 = tid & 63;
    const int p3 = blk * 4 + kslot;            // valid when kslot < 4

    const float wci0 = WC[h0],             wci1 = WC[h0 + 1];
    const float wcf0 = WC[H_DIM + h0],     wcf1 = WC[H_DIM + h0 + 1];
    const float wco0 = WC[2 * H_DIM + h0], wco1 = WC[2 * H_DIM + h0 + 1];

    // lengths dtype detection (int64 vs int32): int32 pair read as int64 is >= 2^32
    long long first = *(const long long*)Lraw;
    long long len3;
    if (first >= 1 && first <= (long long)T_STEPS)
        len3 = ((const long long*)Lraw)[n3];
    else
        len3 = (long long)((const int*)Lraw)[n3];

    float c0 = 0.0f, c1 = 0.0f;
    unsigned sense = 0;

    const float* wbase = s_w + p4 * 8;
    float* buf0 = s_r;
    float* buf1 = s_r + 16384;

    __syncthreads();

    for (int t = 0; t < T_STEPS; t++) {
        // ---- stage r (cp.async, one group) ----
        if (t > 0) {
            for (int i = tid * 4; i < 32768; i += NTHR * 4) cpa16(s_r + i, g_r + i);
            CP_COMMIT();
        }

        // ---- pre[t] loads (overlap with cp.async), K-half 0 threads only ----
        u64t acc[4];
        acc[0] = acc[1] = acc[2] = acc[3] = 0ull;
        if (kh == 0) {
            const int m = t * N_BATCH + n;
            float pvv[8];
#pragma unroll
            for (int g = 0; g < 4; g++)
#pragma unroll
                for (int j = 0; j < 2; j++)
                    pvv[g * 2 + j] =
                        __ldg(g_pre + (size_t)(g * H_DIM + h0 + j) * M_TOTAL + m);
#pragma unroll
            for (int g = 0; g < 4; g++) acc[g] = pk2(pvv[g * 2], pvv[g * 2 + 1]);
        }

        // ---- phase 1: acc += r . wr over this warp's K half ----
        if (t > 0) {
            CP_WAIT0();
            __syncthreads();
            const int kbeg = kh * 256, kend = kbeg + 256;
#pragma unroll 4
            for (int k = kbeg; k < kend; k++) {
                float rv = s_r[k * 64 + n];
                u64t r2 = pk2(rv, rv);
                ulonglong2 wa = *(const ulonglong2*)(wbase + (size_t)k * 32);
                ulonglong2 wb = *(const ulonglong2*)(wbase + (size_t)k * 32 + 4);
                fma2(acc[0], r2, wa.x);
                fma2(acc[1], r2, wa.y);
                fma2(acc[2], r2, wb.x);
                fma2(acc[3], r2, wb.y);
            }
            // K-half reduction through smem
            u64t* red = (u64t*)s_red;
            if (kh == 1) {
                u64t* dst = red + (size_t)(p4 * 64 + n) * 4;
                dst[0] = acc[0]; dst[1] = acc[1]; dst[2] = acc[2]; dst[3] = acc[3];
            }
            __syncthreads();
            if (kh == 0) {
                const u64t* src = red + (size_t)(p4 * 64 + n) * 4;
                acc[0] = add2(acc[0], src[0]);
                acc[1] = add2(acc[1], src[1]);
                acc[2] = add2(acc[2], src[2]);
                acc[3] = add2(acc[3], src[3]);
            }
        }

        // ---- phase 2: gates (K-half 0 threads), h -> g_h ----
        if (kh == 0) {
            float i0, i1, f0, f1, o0, o1, co0, co1;
            unpk2(acc[0], i0, i1); unpk2(acc[1], f0, f1);
            unpk2(acc[2], o0, o1); unpk2(acc[3], co0, co1);

            float in0 = sigmoidf_(i0 + wci0 * c0);
            float fg0 = sigmoidf_(f0 + wcf0 * c0);
            float cc0 = fg0 * c0 + in0 * tanhf_(co0);
            float og0 = sigmoidf_(o0 + wco0 * cc0);
            float hv0 = og0 * tanhf_(cc0);
            c0 = cc0;
            float in1 = sigmoidf_(i1 + wci1 * c1);
            float fg1 = sigmoidf_(f1 + wcf1 * c1);
            float cc1 = fg1 * c1 + in1 * tanhf_(co1);
            float og1 = sigmoidf_(o1 + wco1 * cc1);
            float hv1 = og1 * tanhf_(cc1);
            c1 = cc1;
            __stcg(&g_h[(h0)     * 64 + n], hv0);
            __stcg(&g_h[(h0 + 1) * 64 + n], hv1);
        }

        grid_barrier(sense);   // h complete chip-wide

        // ---- phase 3: r_new[n][p] = h . wo[p], pipelined chunks + 8-way k-split ----
        for (int i = tid * 4; i < 16384; i += NTHR * 4) cpa16(buf0 + i, g_h + i);
        CP_COMMIT();
        for (int i = tid * 4; i < 16384; i += NTHR * 4) cpa16(buf1 + i, g_h + 16384 + i);
        CP_COMMIT();

        u64t a01 = 0ull, a23 = 0ull;
#pragma unroll 1
        for (int ch = 0; ch < 4; ch++) {
            if (ch < 3) CP_WAIT1(); else CP_WAIT0();
            __syncthreads();
            const float* buf = (ch & 1) ? buf1 : buf0;
            const float* wo  = s_wo4 + (size_t)(ch * 256 + kslot * 32) * 4;
            const float* hb  = buf + kslot * 32 * 64 + n3;
#pragma unroll 8
            for (int kk = 0; kk < 32; kk++) {
                float hv = hb[kk * 64];
                u64t h2 = pk2(hv, hv);
                ulonglong2 w4 = *(const ulonglong2*)(wo + kk * 4);
                fma2(a01, h2, w4.x);
                fma2(a23, h2, w4.y);
            }
            __syncthreads();
            if (ch < 2) {   // prefetch chunk ch+2 into the buffer just freed
                float* db = (ch & 1) ? buf1 : buf0;
                const float* src = g_h + (ch + 2) * 16384;
                for (int i = tid * 4; i < 16384; i += NTHR * 4) cpa16(db + i, src + i);
                CP_COMMIT();
            }
        }

        // 8-way reduction: s_red[(p*8 + kslot)*64 + n3]
        {
            float q0, q1, q2, q3;
            unpk2(a01, q0, q1); unpk2(a23, q2, q3);
            s_red[(0 * 8 + kslot) * 64 + n3] = q0;
            s_red[(1 * 8 + kslot) * 64 + n3] = q1;
            s_red[(2 * 8 + kslot) * 64 + n3] = q2;
            s_red[(3 * 8 + kslot) * 64 + n3] = q3;
        }
        __syncthreads();
        if (kslot < 4) {
            const float* rp = s_red + kslot * 8 * 64 + n3;
            float v = 0.0f;
#pragma unroll
            for (int j = 0; j < 8; j++) v += rp[j * 64];
            __stcg(&g_r[p3 * 64 + n3], v);
            out[(size_t)(t * N_BATCH + n3) * P_DIM + p3] = (t < len3) ? v : 0.0f;
        }

        grid_barrier(sense);   // r complete chip-wide
    }
}

// ---------------- launch --------------------------------------------------------------
extern "C" void kernel_launch(void* const* d_in, const int* in_sizes, int n_in,
                              void* d_out, int out_size) {
    const float* x = nullptr;
    const void*  lengths = nullptr;
    const float* wx_w = nullptr;
    const float* wx_b = nullptr;
    const float* wr_w = nullptr;
    const float* wo_w = nullptr;
    const float* wc = nullptr;

    for (int i = 0; i < n_in; i++) {
        int s = in_sizes[i];
        if      (s == T_STEPS * N_BATCH * C_IN) x = (const float*)d_in[i];
        else if (s == N_BATCH)                  lengths = d_in[i];
        else if (s == 4 * H_DIM * C_IN) {
            if (!wx_w) wx_w = (const float*)d_in[i];
            else       wr_w = (const float*)d_in[i];
        }
        else if (s == 4 * H_DIM)                wx_b = (const float*)d_in[i];
        else if (s == P_DIM * H_DIM)            wo_w = (const float*)d_in[i];
        else if (s == 3 * H_DIM)                wc = (const float*)d_in[i];
    }

    const int smem_bytes = (32768 + 16384 + 4096 + 2048) * 4;   // 221184 B = 216 KB
    cudaFuncSetAttribute(lstm_rec, cudaFuncAttributeMaxDynamicSharedMemorySize,
                         smem_bytes);

    dim3 grid1(M_TOTAL / 128, G4H / 64);
    pre_gemm<<<grid1, GTHR>>>(x, wx_w, wx_b);
    lstm_rec<<<NBLK, NTHR, smem_bytes>>>(wr_w, wo_w, wc, lengths, (float*)d_out);
}

// round 6
// speedup vs baseline: 1.5065x; 1.1639x over previous
#include <cuda_runtime.h>
#include <cuda_bf16.h>
#include <cstdint>

#define T_STEPS 512
#define N_BATCH 64
#define C_IN    512
#define H_DIM   1024
#define P_DIM   512
#define G4H     4096
#define M_TOTAL (T_STEPS * N_BATCH)   /* 32768 */
#define NBLK    128
#define NTHR    512                   /* recurrence kernel threads */
#define KSPLIT  1536                  /* bf16-split K: [hi|x:lo/w:hi|x:hi/w:lo] */

typedef unsigned long long u64t;

// ---------------- scratch (device globals: no runtime allocation allowed) -------------
__device__ float g_pre[(size_t)G4H * M_TOTAL];       // pre^T [g][m], 512 MB
__device__ float g_r[P_DIM * N_BATCH];               // r state, [p][n]
__device__ float g_h[H_DIM * N_BATCH];               // gated h, [h][n]
__device__ unsigned g_count;                         // legacy barrier counter
__device__ unsigned g_sense;                         // legacy barrier sense
__device__ unsigned g_flags[NBLK * 64];              // flag barrier: 1 flag / 256B line
__device__ __nv_bfloat16 g_xs[(size_t)M_TOTAL * KSPLIT];  // x split  [m][1536], 96 MB
__device__ __nv_bfloat16 g_ws[(size_t)G4H * KSPLIT];      // wx split [g][1536], 12 MB

// ---------------- f32x2 packed-FMA helpers (sm_100+) ----------------------------------
__device__ __forceinline__ u64t pk2(float lo, float hi) {
    u64t r; asm("mov.b64 %0, {%1, %2};" : "=l"(r) : "f"(lo), "f"(hi)); return r;
}
__device__ __forceinline__ void unpk2(u64t v, float &lo, float &hi) {
    asm("mov.b64 {%0, %1}, %2;" : "=f"(lo), "=f"(hi) : "l"(v));
}
__device__ __forceinline__ void fma2(u64t &d, u64t a, u64t b) {
    asm("fma.rn.f32x2 %0, %1, %2, %0;" : "+l"(d) : "l"(a), "l"(b));
}
__device__ __forceinline__ u64t add2(u64t a, u64t b) {
    u64t r; asm("add.rn.f32x2 %0, %1, %2;" : "=l"(r) : "l"(a), "l"(b)); return r;
}

// ---------------- cp.async helpers ----------------------------------------------------
__device__ __forceinline__ void cpa16(const void* smem_dst, const void* gsrc) {
    uint32_t d = (uint32_t)__cvta_generic_to_shared(smem_dst);
    asm volatile("cp.async.cg.shared.global [%0], [%1], 16;" :: "r"(d), "l"(gsrc));
}
__device__ __forceinline__ void cpa16s(uint32_t smem_dst, const void* gsrc) {
    asm volatile("cp.async.cg.shared.global [%0], [%1], 16;" :: "r"(smem_dst), "l"(gsrc));
}
#define CP_COMMIT() asm volatile("cp.async.commit_group;" ::: "memory")
#define CP_WAIT0()  asm volatile("cp.async.wait_group 0;" ::: "memory")
#define CP_WAIT1()  asm volatile("cp.async.wait_group 1;" ::: "memory")

__device__ __forceinline__ float sigmoidf_(float x) {
    return 1.0f / (1.0f + __expf(-x));
}
__device__ __forceinline__ float tanhf_(float x) {
    float e = __expf(-2.0f * fabsf(x));
    float t = (1.0f - e) / (1.0f + e);
    return copysignf(t, x);
}
__device__ __forceinline__ uint32_t smem_u32(const void* p) {
    return (uint32_t)__cvta_generic_to_shared(p);
}

// ---------------- HMMA helpers (sm_80+ baseline PTX: valid at compute_103) ------------
__device__ __forceinline__ void ldm_x4(uint32_t &r0, uint32_t &r1, uint32_t &r2,
                                       uint32_t &r3, uint32_t a) {
    asm volatile("ldmatrix.sync.aligned.m8n8.x4.shared.b16 {%0,%1,%2,%3}, [%4];"
                 : "=r"(r0), "=r"(r1), "=r"(r2), "=r"(r3) : "r"(a));
}
__device__ __forceinline__ void mma_bf16(float* d, const uint32_t* a, const uint32_t* b) {
    asm volatile("mma.sync.aligned.m16n8k16.row.col.f32.bf16.bf16.f32 "
                 "{%0,%1,%2,%3}, {%4,%5,%6,%7}, {%8,%9}, {%0,%1,%2,%3};"
                 : "+f"(d[0]), "+f"(d[1]), "+f"(d[2]), "+f"(d[3])
                 : "r"(a[0]), "r"(a[1]), "r"(a[2]), "r"(a[3]),
                   "r"(b[0]), "r"(b[1]));
}

// ---------------- legacy atomic grid barrier (2x per lstm_rec launch) -----------------
__device__ __forceinline__ void grid_barrier(unsigned &sense_local) {
    __syncthreads();
    if (threadIdx.x == 0) {
        unsigned s = sense_local ^ 1u;
        unsigned prev;
        asm volatile("atom.acq_rel.gpu.global.add.u32 %0, [%1], %2;"
                     : "=r"(prev) : "l"(&g_count), "r"(1u) : "memory");
        if (prev == gridDim.x - 1) {
            g_count = 0;
            asm volatile("st.release.gpu.global.u32 [%0], %1;"
                         :: "l"(&g_sense), "r"(s) : "memory");
        } else {
            unsigned v;
            do {
                asm volatile("ld.acquire.gpu.global.u32 %0, [%1];"
                             : "=r"(v) : "l"(&g_sense) : "memory");
            } while (v != s);
        }
    }
    __syncthreads();
    sense_local ^= 1u;
}

// ---------------- flag-array grid barrier ---------------------------------------------
// Arrival: thread0 release-stores sequence s to this CTA's own flag (its own 256B line).
// Wait: threads 0..127 each acquire-poll one CTA's flag for >= s. No same-address atomic
// serialization. Flags reset to 0 at launch start behind one legacy barrier, so the
// monotonic in-launch sequence is graph-replay-safe.
__device__ __forceinline__ void flag_barrier(unsigned s) {
    __syncthreads();
    if (threadIdx.x == 0)
        asm volatile("st.release.gpu.global.u32 [%0], %1;"
                     :: "l"(&g_flags[blockIdx.x * 64]), "r"(s) : "memory");
    if (threadIdx.x < NBLK) {
        const unsigned* p = &g_flags[threadIdx.x * 64];
        unsigned v;
        do {
            asm volatile("ld.acquire.gpu.global.u32 %0, [%1];"
                         : "=r"(v) : "l"(p) : "memory");
        } while ((int)(v - s) < 0);
    }
    __syncthreads();
}

// ---------------- Kernel 0: fp32 -> bf16 split, K-concatenated layout -----------------
// mode 0 (x):  dst[row][0:512]=hi, [512:1024]=lo, [1024:1536]=hi
// mode 1 (wx): dst[row][0:512]=hi, [512:1024]=hi, [1024:1536]=lo
// sum over 1536 = hi*hi + hi*lo + lo*hi  (lo*lo term dropped, ~1e-10 rel)
__global__ void split3(const float* __restrict__ src, __nv_bfloat16* __restrict__ dst,
                       int total, int mode) {
    for (int i = blockIdx.x * blockDim.x + threadIdx.x; i < total;
         i += gridDim.x * blockDim.x) {
        int row = i >> 9, k = i & 511;
        float v = src[i];
        __nv_bfloat16 h = __float2bfloat16(v);
        __nv_bfloat16 l = __float2bfloat16(v - __bfloat162float(h));
        __nv_bfloat16* d = dst + (size_t)row * KSPLIT + k;
        d[0] = h;
        d[512]  = mode ? h : l;
        d[1024] = mode ? l : h;
    }
}

// ---------------- Kernel 1: HMMA bf16-split pre-GEMM ----------------------------------
// pre[g][m] = Wsplit[g][:] . Xsplit[m][:] + bias[g].  g on mma-M, m on mma-N, so each
// thread's paired output elements are m-consecutive -> float2 stores to g_pre[g][m].
// CTA: 256g x 128m, 512 thr (16 warps 4x4), warp 64g x 32m, BK=32, double-buffered
// cp.async, 80B-padded smem rows (conflict-free ldmatrix + cp.async).
#define PBM 256
#define PBN 128
#define PBK 32
#define PTHR 512
#define A_STG 20480             /* 256 rows x 80 B */
#define B_STG 10240             /* 128 rows x 80 B */
#define STG   (A_STG + B_STG)
#define PRE_SMEM (2 * STG)      /* 61440 B */

__global__ __launch_bounds__(PTHR, 1)
void hmma_pre(const float* __restrict__ Bb) {
    extern __shared__ char smc[];
    const uint32_t sb = smem_u32(smc);
    const int tid = threadIdx.x, lane = tid & 31, warp = tid >> 5;
    const int wg = warp >> 2;           // g-warp 0..3  (64 g each)
    const int wm = warp & 3;            // m-warp 0..3  (32 m each)
    const int g0 = blockIdx.x * PBM;    // x fastest over g-blocks: B tile L2-shared
    const int m0 = blockIdx.y * PBN;

    float acc[4][4][4];                 // [gi][mj][4]
#pragma unroll
    for (int a = 0; a < 4; a++)
#pragma unroll
        for (int b = 0; b < 4; b++)
#pragma unroll
            for (int c = 0; c < 4; c++) acc[a][b][c] = 0.0f;

    // ldmatrix lane addressing
    const int a_r = lane & 15;
    const int a_k = (lane & 16) ? 8 : 0;
    const int b_r = (lane & 7) + ((lane & 16) ? 8 : 0);
    const int b_k = (lane & 8) ? 8 : 0;

    // per-thread load slots: 3 cp.async of 16B per stage (A:1024 slots, B:512)
#pragma unroll 1
    for (int c = 0; c < KSPLIT / PBK + 1; c++) {
        if (c < KSPLIT / PBK) {          // issue loads for chunk c into stage c&1
            const int k0 = c * PBK;
            const uint32_t ba = sb + (c & 1) * STG;
#pragma unroll
            for (int s = 0; s < 3; s++) {
                int f = tid + s * PTHR;
                if (f < 1024) {
                    int row = f >> 2, seg = f & 3;
                    cpa16s(ba + row * 80 + seg * 16,
                           g_ws + (size_t)(g0 + row) * KSPLIT + k0 + seg * 8);
                } else {
                    int f2 = f - 1024;
                    int row = f2 >> 2, seg = f2 & 3;
                    cpa16s(ba + A_STG + row * 80 + seg * 16,
                           g_xs + (size_t)(m0 + row) * KSPLIT + k0 + seg * 8);
                }
            }
            CP_COMMIT();
        }
        if (c == 0) continue;            // nothing to compute yet
        const int cc = c - 1;            // compute chunk cc (stage cc&1)
        if (c < KSPLIT / PBK) CP_WAIT1(); else CP_WAIT0();
        __syncthreads();

        const uint32_t abase = sb + (cc & 1) * STG + (wg * 64 + a_r) * 80 + a_k * 2;
        const uint32_t bbase = sb + (cc & 1) * STG + A_STG + (wm * 32 + b_r) * 80 + b_k * 2;
#pragma unroll
        for (int kh = 0; kh < 2; kh++) {
            uint32_t af[4][4], bf[2][4];
#pragma unroll
            for (int gi = 0; gi < 4; gi++)
                ldm_x4(af[gi][0], af[gi][1], af[gi][2], af[gi][3],
                       abase + gi * 16 * 80 + kh * 32);
#pragma unroll
            for (int bj = 0; bj < 2; bj++)
                ldm_x4(bf[bj][0], bf[bj][1], bf[bj][2], bf[bj][3],
                       bbase + bj * 16 * 80 + kh * 32);
#pragma unroll
            for (int gi = 0; gi < 4; gi++)
#pragma unroll
                for (int mj = 0; mj < 4; mj++)
                    mma_bf16(acc[gi][mj], af[gi], &bf[mj >> 1][(mj & 1) * 2]);
        }
        __syncthreads();
    }

    // epilogue: bias + float2 stores (m-consecutive pairs)
#pragma unroll
    for (int gi = 0; gi < 4; gi++) {
        const int gr = g0 + wg * 64 + gi * 16 + (lane >> 2);
        const float blo = __ldg(Bb + gr);
        const float bhi = __ldg(Bb + gr + 8);
#pragma unroll
        for (int mj = 0; mj < 4; mj++) {
            const int mc = m0 + wm * 32 + mj * 8 + (lane & 3) * 2;
            float2 v0 = { acc[gi][mj][0] + blo, acc[gi][mj][1] + blo };
            float2 v1 = { acc[gi][mj][2] + bhi, acc[gi][mj][3] + bhi };
            *(float2*)(g_pre + (size_t)gr * M_TOTAL + mc) = v0;
            *(float2*)(g_pre + (size_t)(gr + 8) * M_TOTAL + mc) = v1;
        }
    }
}

// ---------------- Kernel 2: persistent LSTM recurrence --------------------------------
__global__ __launch_bounds__(NTHR)
void lstm_rec(const float* __restrict__ WR, const float* __restrict__ WO,
              const float* __restrict__ WC, const void* __restrict__ Lraw,
              float* __restrict__ out) {
    extern __shared__ float smem[];
    float* s_r   = smem;                    // 32768 f: r[k][n] / 2 x h-chunk[k][n]
    float* s_w   = smem + 32768;            // 16384 f: wr interleaved [k][32]
    float* s_wo4 = smem + 32768 + 16384;    // 4096  f: wo interleaved [k][4]
    float* s_red = smem + 32768 + 16384 + 4096; // 2048 f: cross-split reductions

    const int tid = threadIdx.x;
    const int blk = blockIdx.x;

    // persistent weights, interleaved
    for (int idx = tid; idx < 32 * 512; idx += NTHR) {
        int row = idx >> 9, k = idx & 511;
        int gate = row >> 3, hl = row & 7;
        int col = (hl >> 1) * 8 + gate * 2 + (hl & 1);
        s_w[k * 32 + col] = WR[(size_t)(gate * H_DIM + blk * 8 + hl) * P_DIM + k];
    }
    for (int idx = tid; idx < 4 * 1024; idx += NTHR) {
        int pl = idx >> 10, k = idx & 1023;
        s_wo4[k * 4 + pl] = WO[(size_t)(blk * 4 + pl) * H_DIM + k];
    }

    const int warp = tid >> 5, lane = tid & 31;
    const int n  = (warp & 1) * 32 + lane;
    const int p4 = (warp >> 1) & 3;
    const int kh = warp >> 3;                  // K half
    const int h0 = blk * 8 + p4 * 2;
    const int kslot = tid >> 6;                // 0..7 (phase-3)
    const int n3 = tid & 63;
    const int p3 = blk * 4 + kslot;

    const float wci0 = WC[h0],             wci1 = WC[h0 + 1];
    const float wcf0 = WC[H_DIM + h0],     wcf1 = WC[H_DIM + h0 + 1];
    const float wco0 = WC[2 * H_DIM + h0], wco1 = WC[2 * H_DIM + h0 + 1];

    long long first = *(const long long*)Lraw;
    long long len3;
    if (first >= 1 && first <= (long long)T_STEPS)
        len3 = ((const long long*)Lraw)[n3];
    else
        len3 = (long long)((const int*)Lraw)[n3];

    float c0 = 0.0f, c1 = 0.0f;
    unsigned sense = 0;

    const float* wbase = s_w + p4 * 8;
    float* buf0 = s_r;
    float* buf1 = s_r + 16384;

    // reset own flag, then one atomic barrier so all resets are visible everywhere
    if (tid == 0) g_flags[blk * 64] = 0u;
    grid_barrier(sense);

    unsigned barno = 0;

    for (int t = 0; t < T_STEPS; t++) {
        if (t > 0) {
            for (int i = tid * 4; i < 32768; i += NTHR * 4) cpa16(s_r + i, g_r + i);
            CP_COMMIT();
        }

        u64t acc[4];
        acc[0] = acc[1] = acc[2] = acc[3] = 0ull;
        if (kh == 0) {
            const int m = t * N_BATCH + n;
            float pvv[8];
#pragma unroll
            for (int g = 0; g < 4; g++)
#pragma unroll
                for (int j = 0; j < 2; j++)
                    pvv[g * 2 + j] =
                        __ldg(g_pre + (size_t)(g * H_DIM + h0 + j) * M_TOTAL + m);
#pragma unroll
            for (int g = 0; g < 4; g++) acc[g] = pk2(pvv[g * 2], pvv[g * 2 + 1]);
        }

        if (t > 0) {
            CP_WAIT0();
            __syncthreads();
            const int kbeg = kh * 256, kend = kbeg + 256;
#pragma unroll 4
            for (int k = kbeg; k < kend; k++) {
                float rv = s_r[k * 64 + n];
                u64t r2 = pk2(rv, rv);
                ulonglong2 wa = *(const ulonglong2*)(wbase + (size_t)k * 32);
                ulonglong2 wb = *(const ulonglong2*)(wbase + (size_t)k * 32 + 4);
                fma2(acc[0], r2, wa.x);
                fma2(acc[1], r2, wa.y);
                fma2(acc[2], r2, wb.x);
                fma2(acc[3], r2, wb.y);
            }
            u64t* red = (u64t*)s_red;
            if (kh == 1) {
                u64t* dst = red + (size_t)(p4 * 64 + n) * 4;
                dst[0] = acc[0]; dst[1] = acc[1]; dst[2] = acc[2]; dst[3] = acc[3];
            }
            __syncthreads();
            if (kh == 0) {
                const u64t* src = red + (size_t)(p4 * 64 + n) * 4;
                acc[0] = add2(acc[0], src[0]);
                acc[1] = add2(acc[1], src[1]);
                acc[2] = add2(acc[2], src[2]);
                acc[3] = add2(acc[3], src[3]);
            }
        }

        if (kh == 0) {
            float i0, i1, f0, f1, o0, o1, co0, co1;
            unpk2(acc[0], i0, i1); unpk2(acc[1], f0, f1);
            unpk2(acc[2], o0, o1); unpk2(acc[3], co0, co1);

            float in0 = sigmoidf_(i0 + wci0 * c0);
            float fg0 = sigmoidf_(f0 + wcf0 * c0);
            float cc0 = fg0 * c0 + in0 * tanhf_(co0);
            float og0 = sigmoidf_(o0 + wco0 * cc0);
            float hv0 = og0 * tanhf_(cc0);
            c0 = cc0;
            float in1 = sigmoidf_(i1 + wci1 * c1);
            float fg1 = sigmoidf_(f1 + wcf1 * c1);
            float cc1 = fg1 * c1 + in1 * tanhf_(co1);
            float og1 = sigmoidf_(o1 + wco1 * cc1);
            float hv1 = og1 * tanhf_(cc1);
            c1 = cc1;
            __stcg(&g_h[(h0)     * 64 + n], hv0);
            __stcg(&g_h[(h0 + 1) * 64 + n], hv1);
        }

        flag_barrier(++barno);   // h complete chip-wide

        // phase 3: r_new = h . wo, pipelined chunks + 8-way k-split
        for (int i = tid * 4; i < 16384; i += NTHR * 4) cpa16(buf0 + i, g_h + i);
        CP_COMMIT();
        for (int i = tid * 4; i < 16384; i += NTHR * 4) cpa16(buf1 + i, g_h + 16384 + i);
        CP_COMMIT();

        u64t a01 = 0ull, a23 = 0ull;
#pragma unroll 1
        for (int ch = 0; ch < 4; ch++) {
            if (ch < 3) CP_WAIT1(); else CP_WAIT0();
            __syncthreads();
            const float* buf = (ch & 1) ? buf1 : buf0;
            const float* wo  = s_wo4 + (size_t)(ch * 256 + kslot * 32) * 4;
            const float* hb  = buf + kslot * 32 * 64 + n3;
#pragma unroll 8
            for (int kk = 0; kk < 32; kk++) {
                float hv = hb[kk * 64];
                u64t h2 = pk2(hv, hv);
                ulonglong2 w4 = *(const ulonglong2*)(wo + kk * 4);
                fma2(a01, h2, w4.x);
                fma2(a23, h2, w4.y);
            }
            __syncthreads();
            if (ch < 2) {
                float* db = (ch & 1) ? buf1 : buf0;
                const float* src = g_h + (ch + 2) * 16384;
                for (int i = tid * 4; i < 16384; i += NTHR * 4) cpa16(db + i, src + i);
                CP_COMMIT();
            }
        }

        {
            float q0, q1, q2, q3;
            unpk2(a01, q0, q1); unpk2(a23, q2, q3);
            s_red[(0 * 8 + kslot) * 64 + n3] = q0;
            s_red[(1 * 8 + kslot) * 64 + n3] = q1;
            s_red[(2 * 8 + kslot) * 64 + n3] = q2;
            s_red[(3 * 8 + kslot) * 64 + n3] = q3;
        }
        __syncthreads();
        if (kslot < 4) {
            const float* rp = s_red + kslot * 8 * 64 + n3;
            float v = 0.0f;
#pragma unroll
            for (int j = 0; j < 8; j++) v += rp[j * 64];
            __stcg(&g_r[p3 * 64 + n3], v);
            out[(size_t)(t * N_BATCH + n3) * P_DIM + p3] = (t < len3) ? v : 0.0f;
        }

        flag_barrier(++barno);   // r complete chip-wide
    }

    grid_barrier(sense);   // g_sense returns to its launch-entry value (replay-safe)
}

// ---------------- launch --------------------------------------------------------------
extern "C" void kernel_launch(void* const* d_in, const int* in_sizes, int n_in,
                              void* d_out, int out_size) {
    const float* x = nullptr;
    const void*  lengths = nullptr;
    const float* wx_w = nullptr;
    const float* wx_b = nullptr;
    const float* wr_w = nullptr;
    const float* wo_w = nullptr;
    const float* wc = nullptr;

    for (int i = 0; i < n_in; i++) {
        int s = in_sizes[i];
        if      (s == T_STEPS * N_BATCH * C_IN) x = (const float*)d_in[i];
        else if (s == N_BATCH)                  lengths = d_in[i];
        else if (s == 4 * H_DIM * C_IN) {
            if (!wx_w) wx_w = (const float*)d_in[i];
            else       wr_w = (const float*)d_in[i];
        }
        else if (s == 4 * H_DIM)                wx_b = (const float*)d_in[i];
        else if (s == P_DIM * H_DIM)            wo_w = (const float*)d_in[i];
        else if (s == 3 * H_DIM)                wc = (const float*)d_in[i];
    }

    __nv_bfloat16 *xs, *ws;
    cudaGetSymbolAddress((void**)&xs, g_xs);
    cudaGetSymbolAddress((void**)&ws, g_ws);

    // bf16 splits, K-concatenated
    split3<<<4096, 256>>>(x,    xs, M_TOTAL * C_IN, 0);
    split3<<<1024, 256>>>(wx_w, ws, G4H * C_IN, 1);

    // HMMA pre-GEMM
    cudaFuncSetAttribute(hmma_pre, cudaFuncAttributeMaxDynamicSharedMemorySize, PRE_SMEM);
    dim3 gridp(G4H / PBM, M_TOTAL / PBN);   // x = g-blocks (fastest): B tile L2-shared
    hmma_pre<<<gridp, PTHR, PRE_SMEM>>>(wx_b);

    // recurrence
    const int smem_bytes = (32768 + 16384 + 4096 + 2048) * 4;
    cudaFuncSetAttribute(lstm_rec, cudaFuncAttributeMaxDynamicSharedMemorySize,
                         smem_bytes);
    lstm_rec<<<NBLK, NTHR, smem_bytes>>>(wr_w, wo_w, wc, lengths, (float*)d_out);
}

// round 7
// speedup vs baseline: 2.0559x; 1.3647x over previous
#include <cuda_runtime.h>
#include <cuda_bf16.h>
#include <cstdint>

#define T_STEPS 512
#define N_BATCH 64
#define C_IN    512
#define H_DIM   1024
#define P_DIM   512
#define G4H     4096
#define M_TOTAL (T_STEPS * N_BATCH)   /* 32768 */
#define NBLK    128
#define NTHR    512
#define KSPLIT  1536                  /* pre-GEMM bf16-split K */

typedef unsigned long long u64t;

// ---------------- scratch (device globals: no runtime allocation allowed) -------------
__device__ float g_pre[(size_t)G4H * M_TOTAL];        // pre^T [g][m], 512 MB
__device__ __nv_bfloat16 g_rb[N_BATCH * 1024];        // r state: [n][hi 512 | lo 512]
__device__ __nv_bfloat16 g_hb[N_BATCH * 2048];        // h state: [n][hi 1024 | lo 1024]
__device__ unsigned g_count;                          // legacy barrier counter
__device__ unsigned g_sense;                          // legacy barrier sense
__device__ unsigned g_flags[NBLK * 64];               // flag barrier: 1 flag / 256B line
__device__ __nv_bfloat16 g_xs[(size_t)M_TOTAL * KSPLIT];  // x split  [m][1536]
__device__ __nv_bfloat16 g_ws[(size_t)G4H * KSPLIT];      // wx split [g][1536]

// ---------------- small helpers --------------------------------------------------------
__device__ __forceinline__ void cpa16s(uint32_t smem_dst, const void* gsrc) {
    asm volatile("cp.async.cg.shared.global [%0], [%1], 16;" :: "r"(smem_dst), "l"(gsrc));
}
#define CP_COMMIT() asm volatile("cp.async.commit_group;" ::: "memory")
#define CP_WAIT0()  asm volatile("cp.async.wait_group 0;" ::: "memory")
#define CP_WAIT1()  asm volatile("cp.async.wait_group 1;" ::: "memory")

__device__ __forceinline__ float sigmoidf_(float x) {
    return 1.0f / (1.0f + __expf(-x));
}
__device__ __forceinline__ float tanhf_(float x) {
    float e = __expf(-2.0f * fabsf(x));
    float t = (1.0f - e) / (1.0f + e);
    return copysignf(t, x);
}
__device__ __forceinline__ uint32_t smem_u32(const void* p) {
    return (uint32_t)__cvta_generic_to_shared(p);
}
__device__ __forceinline__ void stcg_u32(void* p, uint32_t v) {
    asm volatile("st.global.cg.u32 [%0], %1;" :: "l"(p), "r"(v) : "memory");
}
__device__ __forceinline__ void stcg_u16(void* p, unsigned short v) {
    asm volatile("st.global.cg.u16 [%0], %1;" :: "l"(p), "h"(v) : "memory");
}
__device__ __forceinline__ unsigned short bf_bits(__nv_bfloat16 h) {
    unsigned short u; __builtin_memcpy(&u, &h, 2); return u;
}

// ---------------- HMMA helpers (sm_80+ baseline PTX: valid at compute_103) ------------
__device__ __forceinline__ void ldm_x4(uint32_t &r0, uint32_t &r1, uint32_t &r2,
                                       uint32_t &r3, uint32_t a) {
    asm volatile("ldmatrix.sync.aligned.m8n8.x4.shared.b16 {%0,%1,%2,%3}, [%4];"
                 : "=r"(r0), "=r"(r1), "=r"(r2), "=r"(r3) : "r"(a));
}
__device__ __forceinline__ void ldm_x2(uint32_t &r0, uint32_t &r1, uint32_t a) {
    asm volatile("ldmatrix.sync.aligned.m8n8.x2.shared.b16 {%0,%1}, [%2];"
                 : "=r"(r0), "=r"(r1) : "r"(a));
}
__device__ __forceinline__ void mma_bf16(float* d, const uint32_t* a, const uint32_t* b) {
    asm volatile("mma.sync.aligned.m16n8k16.row.col.f32.bf16.bf16.f32 "
                 "{%0,%1,%2,%3}, {%4,%5,%6,%7}, {%8,%9}, {%0,%1,%2,%3};"
                 : "+f"(d[0]), "+f"(d[1]), "+f"(d[2]), "+f"(d[3])
                 : "r"(a[0]), "r"(a[1]), "r"(a[2]), "r"(a[3]),
                   "r"(b[0]), "r"(b[1]));
}

// ---------------- legacy atomic grid barrier (2x per lstm_rec launch) -----------------
__device__ __forceinline__ void grid_barrier(unsigned &sense_local) {
    __syncthreads();
    if (threadIdx.x == 0) {
        unsigned s = sense_local ^ 1u;
        unsigned prev;
        asm volatile("atom.acq_rel.gpu.global.add.u32 %0, [%1], %2;"
                     : "=r"(prev) : "l"(&g_count), "r"(1u) : "memory");
        if (prev == gridDim.x - 1) {
            g_count = 0;
            asm volatile("st.release.gpu.global.u32 [%0], %1;"
                         :: "l"(&g_sense), "r"(s) : "memory");
        } else {
            unsigned v;
            do {
                asm volatile("ld.acquire.gpu.global.u32 %0, [%1];"
                             : "=r"(v) : "l"(&g_sense) : "memory");
            } while (v != s);
        }
    }
    __syncthreads();
    sense_local ^= 1u;
}

// ---------------- flag-array grid barrier ----------------------------------------------
__device__ __forceinline__ void flag_barrier(unsigned s) {
    __syncthreads();
    if (threadIdx.x == 0)
        asm volatile("st.release.gpu.global.u32 [%0], %1;"
                     :: "l"(&g_flags[blockIdx.x * 64]), "r"(s) : "memory");
    if (threadIdx.x < NBLK) {
        const unsigned* p = &g_flags[threadIdx.x * 64];
        unsigned v;
        do {
            asm volatile("ld.acquire.gpu.global.u32 %0, [%1];"
                         : "=r"(v) : "l"(p) : "memory");
        } while ((int)(v - s) < 0);
    }
    __syncthreads();
}

// ---------------- Kernel 0: fp32 -> bf16 split, K-concatenated (pre-GEMM operands) ----
__global__ void split3(const float* __restrict__ src, __nv_bfloat16* __restrict__ dst,
                       int total, int mode) {
    for (int i = blockIdx.x * blockDim.x + threadIdx.x; i < total;
         i += gridDim.x * blockDim.x) {
        int row = i >> 9, k = i & 511;
        float v = src[i];
        __nv_bfloat16 h = __float2bfloat16(v);
        __nv_bfloat16 l = __float2bfloat16(v - __bfloat162float(h));
        __nv_bfloat16* d = dst + (size_t)row * KSPLIT + k;
        d[0] = h;
        d[512]  = mode ? h : l;
        d[1024] = mode ? l : h;
    }
}

// ---------------- Kernel 1: HMMA bf16-split pre-GEMM (unchanged from R5, passing) -----
#define PBM 256
#define PBN 128
#define PTHR 512
#define A_STG 20480
#define B_STG 10240
#define STG   (A_STG + B_STG)
#define PRE_SMEM (2 * STG)

__global__ __launch_bounds__(PTHR, 1)
void hmma_pre(const float* __restrict__ Bb) {
    extern __shared__ char smc[];
    const uint32_t sb = smem_u32(smc);
    const int tid = threadIdx.x, lane = tid & 31, warp = tid >> 5;
    const int wg = warp >> 2;
    const int wm = warp & 3;
    const int g0 = blockIdx.x * PBM;
    const int m0 = blockIdx.y * PBN;

    float acc[4][4][4];
#pragma unroll
    for (int a = 0; a < 4; a++)
#pragma unroll
        for (int b = 0; b < 4; b++)
#pragma unroll
            for (int c = 0; c < 4; c++) acc[a][b][c] = 0.0f;

    const int a_r = lane & 15;
    const int a_k = (lane & 16) ? 8 : 0;
    const int b_r = (lane & 7) + ((lane & 16) ? 8 : 0);
    const int b_k = (lane & 8) ? 8 : 0;

#pragma unroll 1
    for (int c = 0; c < KSPLIT / 32 + 1; c++) {
        if (c < KSPLIT / 32) {
            const int k0 = c * 32;
            const uint32_t ba = sb + (c & 1) * STG;
#pragma unroll
            for (int s = 0; s < 3; s++) {
                int f = tid + s * PTHR;
                if (f < 1024) {
                    int row = f >> 2, seg = f & 3;
                    cpa16s(ba + row * 80 + seg * 16,
                           g_ws + (size_t)(g0 + row) * KSPLIT + k0 + seg * 8);
                } else {
                    int f2 = f - 1024;
                    int row = f2 >> 2, seg = f2 & 3;
                    cpa16s(ba + A_STG + row * 80 + seg * 16,
                           g_xs + (size_t)(m0 + row) * KSPLIT + k0 + seg * 8);
                }
            }
            CP_COMMIT();
        }
        if (c == 0) continue;
        const int cc = c - 1;
        if (c < KSPLIT / 32) CP_WAIT1(); else CP_WAIT0();
        __syncthreads();

        const uint32_t abase = sb + (cc & 1) * STG + (wg * 64 + a_r) * 80 + a_k * 2;
        const uint32_t bbase = sb + (cc & 1) * STG + A_STG + (wm * 32 + b_r) * 80 + b_k * 2;
#pragma unroll
        for (int kh = 0; kh < 2; kh++) {
            uint32_t af[4][4], bf[2][4];
#pragma unroll
            for (int gi = 0; gi < 4; gi++)
                ldm_x4(af[gi][0], af[gi][1], af[gi][2], af[gi][3],
                       abase + gi * 16 * 80 + kh * 32);
#pragma unroll
            for (int bj = 0; bj < 2; bj++)
                ldm_x4(bf[bj][0], bf[bj][1], bf[bj][2], bf[bj][3],
                       bbase + bj * 16 * 80 + kh * 32);
#pragma unroll
            for (int gi = 0; gi < 4; gi++)
#pragma unroll
                for (int mj = 0; mj < 4; mj++)
                    mma_bf16(acc[gi][mj], af[gi], &bf[mj >> 1][(mj & 1) * 2]);
        }
        __syncthreads();
    }

#pragma unroll
    for (int gi = 0; gi < 4; gi++) {
        const int gr = g0 + wg * 64 + gi * 16 + (lane >> 2);
        const float blo = __ldg(Bb + gr);
        const float bhi = __ldg(Bb + gr + 8);
#pragma unroll
        for (int mj = 0; mj < 4; mj++) {
            const int mc = m0 + wm * 32 + mj * 8 + (lane & 3) * 2;
            float2 v0 = { acc[gi][mj][0] + blo, acc[gi][mj][1] + blo };
            float2 v1 = { acc[gi][mj][2] + bhi, acc[gi][mj][3] + bhi };
            *(float2*)(g_pre + (size_t)gr * M_TOTAL + mc) = v0;
            *(float2*)(g_pre + (size_t)(gr + 8) * M_TOTAL + mc) = v1;
        }
    }
}

// ---------------- Kernel 2: persistent LSTM recurrence (HMMA phases 1+3) --------------
// smem layout (bytes):
//   REG   @ 0       size 133120 : time-multiplexed
//            t>0: r staged [n(64)][1024 bf16] pitch 2064
//            then phase-1 partials: fp32 [kq(4)][n(64)][gcol pad 38]  (38912 B)
//            then h chunks: 2 x ([n(64)][512 bf16] pitch 1040 = 66560)
//            then phase-3 partials: fp32 [kq(4)][n(64)][p pad 6]      (6144 B)
//   W1HI  @ 133120  size 33280 : [gcol(32)][512 bf16] pitch 1040
//   W1LO  @ 166400  size 33280
//   WOHI  @ 199680  size 8256  : [p(4)][1024 bf16] pitch 2064
//   WOLO  @ 207936  size 8256
#define R_REG   0
#define R_W1HI  133120
#define R_W1LO  166400
#define R_WOHI  199680
#define R_WOLO  207936
#define REC_SMEM 216192
#define HBUF1   66560

__global__ __launch_bounds__(NTHR, 1)
void lstm_rec(const float* __restrict__ WR, const float* __restrict__ WO,
              const float* __restrict__ WC, const void* __restrict__ Lraw,
              float* __restrict__ out) {
    extern __shared__ char sm[];
    const uint32_t sb = smem_u32(sm);
    float* part  = (float*)(sm + R_REG);      // phase-1 partials (after r dies)
    float* part3 = (float*)(sm + R_REG);      // phase-3 partials (after h chunks die)

    const int tid = threadIdx.x;
    const int blk = blockIdx.x;
    const int lane = tid & 31, warp = tid >> 5;

    // ---- build static weights in smem (bf16 hi/lo) ----
    {
        __nv_bfloat16* w1h = (__nv_bfloat16*)(sm + R_W1HI);
        __nv_bfloat16* w1l = (__nv_bfloat16*)(sm + R_W1LO);
        for (int idx = tid; idx < 32 * 512; idx += NTHR) {
            int gcol = idx >> 9, k = idx & 511;
            int gate = gcol >> 3, hl = gcol & 7;
            float v = WR[(size_t)(gate * H_DIM + blk * 8 + hl) * P_DIM + k];
            __nv_bfloat16 h = __float2bfloat16(v);
            w1h[gcol * 520 + k] = h;
            w1l[gcol * 520 + k] = __float2bfloat16(v - __bfloat162float(h));
        }
        __nv_bfloat16* woh = (__nv_bfloat16*)(sm + R_WOHI);
        __nv_bfloat16* wol = (__nv_bfloat16*)(sm + R_WOLO);
        for (int idx = tid; idx < 4 * 1024; idx += NTHR) {
            int p = idx >> 10, k = idx & 1023;
            float v = WO[(size_t)(blk * 4 + p) * H_DIM + k];
            __nv_bfloat16 h = __float2bfloat16(v);
            woh[p * 1032 + k] = h;
            wol[p * 1032 + k] = __float2bfloat16(v - __bfloat162float(h));
        }
    }

    // ---- roles ----
    // phase-1 mma: warp = kq1*4 + ng*2 + mh
    const int mh  = warp & 1;          // n-rows mh*32 + [0,32)
    const int ng  = (warp >> 1) & 1;   // gcols ng*16 + [0,16)
    const int kq1 = warp >> 2;         // orig-k quarter (128 k)
    // phase-2 (warps 0-7): fixed c-state ownership
    const int n2 = (warp >> 2) * 32 + lane;   // batch index (valid warp<8)
    const int hp = warp & 3;
    const int h0 = blk * 8 + hp * 2;
    // phase-3 mma: warp = kq3*4 + mh3
    const int mh3 = warp & 3;          // n-rows mh3*16 + [0,16)
    const int kq3 = warp >> 2;         // k quarter within chunk (4 k16)
    // phase-3 reduce: tid<256
    const int nr = tid >> 2, pr = tid & 3;
    const int pg = blk * 4 + pr;

    // ldmatrix lane addressing (same formulas as hmma_pre, verified passing)
    const int a_r  = lane & 15;
    const int a_kb = (lane & 16) ? 16 : 0;    // bytes
    const int b_r  = (lane & 7) + ((lane & 16) ? 8 : 0);
    const int b_kb = (lane & 8) ? 16 : 0;     // bytes

    const float wci0 = WC[h0],             wci1 = WC[h0 + 1];
    const float wcf0 = WC[H_DIM + h0],     wcf1 = WC[H_DIM + h0 + 1];
    const float wco0 = WC[2 * H_DIM + h0], wco1 = WC[2 * H_DIM + h0 + 1];

    // lengths dtype detection (int64 vs int32)
    long long first = *(const long long*)Lraw;
    long long len_r;
    if (first >= 1 && first <= (long long)T_STEPS)
        len_r = ((const long long*)Lraw)[nr];
    else
        len_r = (long long)((const int*)Lraw)[nr];

    float c0 = 0.0f, c1 = 0.0f;
    unsigned sense = 0;

    if (tid == 0) g_flags[blk * 64] = 0u;
    grid_barrier(sense);

    unsigned barno = 0;

#pragma unroll 1
    for (int t = 0; t < T_STEPS; t++) {
        // ---- stage r (bf16 hi|lo, 64 rows x 2048B, pitch 2064) ----
        if (t > 0) {
            for (int g = tid; g < 8192; g += NTHR) {
                int row = g >> 7, gi = g & 127;
                cpa16s(sb + R_REG + row * 2064 + gi * 16,
                       (const char*)g_rb + row * 2048 + gi * 16);
            }
            CP_COMMIT();
        }

        // ---- pre[t] loads (phase-2 owners), overlap with staging ----
        float pv[8];
        if (warp < 8) {
            const int m = t * N_BATCH + n2;
#pragma unroll
            for (int g = 0; g < 4; g++)
#pragma unroll
                for (int j = 0; j < 2; j++)
                    pv[g * 2 + j] =
                        __ldg(g_pre + (size_t)(g * H_DIM + h0 + j) * M_TOTAL + m);
        }

        // ---- phase 1: partial[n][gcol] = r . wr  (bf16-split HMMA) ----
        if (t > 0) {
            CP_WAIT0();
            __syncthreads();

            float acc[2][2][4];
#pragma unroll
            for (int a = 0; a < 2; a++)
#pragma unroll
                for (int b = 0; b < 2; b++)
#pragma unroll
                    for (int c = 0; c < 4; c++) acc[a][b][c] = 0.0f;

#pragma unroll 2
            for (int j = 0; j < 8; j++) {
                const int kb = (kq1 * 128 + j * 16) * 2;   // byte offset in hi block
                uint32_t bh[4], bl[4];
                const uint32_t brow = (uint32_t)(ng * 16 + b_r);
                ldm_x4(bh[0], bh[1], bh[2], bh[3],
                       sb + R_W1HI + brow * 1040 + kb + b_kb);
                ldm_x4(bl[0], bl[1], bl[2], bl[3],
                       sb + R_W1LO + brow * 1040 + kb + b_kb);
#pragma unroll
                for (int mi = 0; mi < 2; mi++) {
                    const uint32_t arow = (uint32_t)(mh * 32 + mi * 16 + a_r);
                    uint32_t ah[4], al[4];
                    ldm_x4(ah[0], ah[1], ah[2], ah[3],
                           sb + R_REG + arow * 2064 + kb + a_kb);
                    ldm_x4(al[0], al[1], al[2], al[3],
                           sb + R_REG + arow * 2064 + 1024 + kb + a_kb);
#pragma unroll
                    for (int nj = 0; nj < 2; nj++) {
                        mma_bf16(acc[mi][nj], ah, &bh[nj * 2]);
                        mma_bf16(acc[mi][nj], al, &bh[nj * 2]);
                        mma_bf16(acc[mi][nj], ah, &bl[nj * 2]);
                    }
                }
            }
            __syncthreads();   // all r reads done before partials overwrite region

            // partial layout: [kq][n][38] fp32
#pragma unroll
            for (int mi = 0; mi < 2; mi++)
#pragma unroll
                for (int nj = 0; nj < 2; nj++) {
                    const int n  = mh * 32 + mi * 16 + (lane >> 2);
                    const int gc = ng * 16 + nj * 8 + (lane & 3) * 2;
                    float2 v0 = { acc[mi][nj][0], acc[mi][nj][1] };
                    float2 v1 = { acc[mi][nj][2], acc[mi][nj][3] };
                    *(float2*)&part[(kq1 * 64 + n) * 38 + gc] = v0;
                    *(float2*)&part[(kq1 * 64 + n + 8) * 38 + gc] = v1;
                }
            __syncthreads();
        }

        // ---- phase 2: gates (warps 0-7 own (n2, h0/h0+1); c in registers) ----
        if (warp < 8) {
            float gv[8];
#pragma unroll
            for (int q = 0; q < 8; q++) gv[q] = pv[q];
            if (t > 0) {
#pragma unroll
                for (int gate = 0; gate < 4; gate++) {
                    const int gc = gate * 8 + hp * 2;
#pragma unroll
                    for (int kq = 0; kq < 4; kq++) {
                        float2 v = *(const float2*)&part[(kq * 64 + n2) * 38 + gc];
                        gv[gate * 2]     += v.x;
                        gv[gate * 2 + 1] += v.y;
                    }
                }
            }
            float in0 = sigmoidf_(gv[0] + wci0 * c0);
            float fg0 = sigmoidf_(gv[2] + wcf0 * c0);
            float cc0 = fg0 * c0 + in0 * tanhf_(gv[6]);
            float og0 = sigmoidf_(gv[4] + wco0 * cc0);
            float hv0 = og0 * tanhf_(cc0);
            c0 = cc0;
            float in1 = sigmoidf_(gv[1] + wci1 * c1);
            float fg1 = sigmoidf_(gv[3] + wcf1 * c1);
            float cc1 = fg1 * c1 + in1 * tanhf_(gv[7]);
            float og1 = sigmoidf_(gv[5] + wco1 * cc1);
            float hv1 = og1 * tanhf_(cc1);
            c1 = cc1;

            __nv_bfloat16 h0b = __float2bfloat16(hv0);
            __nv_bfloat16 h1b = __float2bfloat16(hv1);
            __nv_bfloat16 l0b = __float2bfloat16(hv0 - __bfloat162float(h0b));
            __nv_bfloat16 l1b = __float2bfloat16(hv1 - __bfloat162float(h1b));
            uint32_t hi2 = (uint32_t)bf_bits(h0b) | ((uint32_t)bf_bits(h1b) << 16);
            uint32_t lo2 = (uint32_t)bf_bits(l0b) | ((uint32_t)bf_bits(l1b) << 16);
            stcg_u32(g_hb + n2 * 2048 + h0, hi2);
            stcg_u32(g_hb + n2 * 2048 + 1024 + h0, lo2);
        }

        flag_barrier(++barno);   // h complete chip-wide

        // ---- phase 3: r_new[n][p] = h . wo  (bf16-split HMMA, 4 h-chunks) ----
        // stage chunks 0,1 (chunk c: [n][hi 256k | lo 256k] bf16, pitch 1040)
#pragma unroll
        for (int c0i = 0; c0i < 2; c0i++) {
            const uint32_t hb = sb + R_REG + c0i * HBUF1;
            for (int g = tid; g < 4096; g += NTHR) {
                int row = g >> 6, gi = g & 63;
                if (gi < 32)
                    cpa16s(hb + row * 1040 + gi * 16,
                           (const char*)g_hb + row * 4096 + c0i * 512 + gi * 16);
                else
                    cpa16s(hb + row * 1040 + 512 + (gi - 32) * 16,
                           (const char*)g_hb + row * 4096 + 2048 + c0i * 512 + (gi - 32) * 16);
            }
            CP_COMMIT();
        }

        float acc3[4] = {0.0f, 0.0f, 0.0f, 0.0f};
#pragma unroll 1
        for (int c = 0; c < 4; c++) {
            if (c < 3) CP_WAIT1(); else CP_WAIT0();
            __syncthreads();
            const uint32_t hb = sb + R_REG + (c & 1) * HBUF1;
#pragma unroll
            for (int j = 0; j < 4; j++) {
                const int jj = kq3 * 4 + j;            // k16 index within chunk
                const int kb = jj * 32;                // byte offset in chunk hi part
                uint32_t ah[4], al[4], bh[2], bl[2];
                const uint32_t arow = (uint32_t)(mh3 * 16 + a_r);
                ldm_x4(ah[0], ah[1], ah[2], ah[3], hb + arow * 1040 + kb + a_kb);
                ldm_x4(al[0], al[1], al[2], al[3], hb + arow * 1040 + 512 + kb + a_kb);
                const int kob = (c * 256 + jj * 16) * 2;   // byte offset into Wo rows
                const uint32_t brow = (uint32_t)(lane & 3); // cols 4-7 duplicate 0-3
                ldm_x2(bh[0], bh[1], sb + R_WOHI + brow * 2064 + kob + b_kb);
                ldm_x2(bl[0], bl[1], sb + R_WOLO + brow * 2064 + kob + b_kb);
                mma_bf16(acc3, ah, bh);
                mma_bf16(acc3, al, bh);
                mma_bf16(acc3, ah, bl);
            }
            __syncthreads();
            if (c < 2) {   // stage chunk c+2 into the buffer just freed
                const uint32_t db = sb + R_REG + (c & 1) * HBUF1;
                const int cc = c + 2;
                for (int g = tid; g < 4096; g += NTHR) {
                    int row = g >> 6, gi = g & 63;
                    if (gi < 32)
                        cpa16s(db + row * 1040 + gi * 16,
                               (const char*)g_hb + row * 4096 + cc * 512 + gi * 16);
                    else
                        cpa16s(db + row * 1040 + 512 + (gi - 32) * 16,
                               (const char*)g_hb + row * 4096 + 2048 + cc * 512 + (gi - 32) * 16);
                }
                CP_COMMIT();
            }
        }
        __syncthreads();

        // phase-3 partials: [kq][n][6] fp32 (only real p cols 0-3: lanes (lane&3)<2)
        if ((lane & 3) < 2) {
            const int n = mh3 * 16 + (lane >> 2);
            const int pc = (lane & 3) * 2;
            float2 v0 = { acc3[0], acc3[1] };
            float2 v1 = { acc3[2], acc3[3] };
            *(float2*)&part3[(kq3 * 64 + n) * 6 + pc] = v0;
            *(float2*)&part3[(kq3 * 64 + n + 8) * 6 + pc] = v1;
        }
        __syncthreads();

        if (tid < 256) {
            float v = 0.0f;
#pragma unroll
            for (int kq = 0; kq < 4; kq++) v += part3[(kq * 64 + nr) * 6 + pr];
            out[(size_t)(t * N_BATCH + nr) * P_DIM + pg] = (t < len_r) ? v : 0.0f;
            __nv_bfloat16 hb16 = __float2bfloat16(v);
            __nv_bfloat16 lb16 = __float2bfloat16(v - __bfloat162float(hb16));
            stcg_u16(g_rb + nr * 1024 + pg, bf_bits(hb16));
            stcg_u16(g_rb + nr * 1024 + 512 + pg, bf_bits(lb16));
        }

        flag_barrier(++barno);   // r complete chip-wide
    }

    grid_barrier(sense);   // g_sense returns to launch-entry value (replay-safe)
}

// ---------------- launch ----------------------------------------------------------------
extern "C" void kernel_launch(void* const* d_in, const int* in_sizes, int n_in,
                              void* d_out, int out_size) {
    const float* x = nullptr;
    const void*  lengths = nullptr;
    const float* wx_w = nullptr;
    const float* wx_b = nullptr;
    const float* wr_w = nullptr;
    const float* wo_w = nullptr;
    const float* wc = nullptr;

    for (int i = 0; i < n_in; i++) {
        int s = in_sizes[i];
        if      (s == T_STEPS * N_BATCH * C_IN) x = (const float*)d_in[i];
        else if (s == N_BATCH)                  lengths = d_in[i];
        else if (s == 4 * H_DIM * C_IN) {
            if (!wx_w) wx_w = (const float*)d_in[i];
            else       wr_w = (const float*)d_in[i];
        }
        else if (s == 4 * H_DIM)                wx_b = (const float*)d_in[i];
        else if (s == P_DIM * H_DIM)            wo_w = (const float*)d_in[i];
        else if (s == 3 * H_DIM)                wc = (const float*)d_in[i];
    }

    __nv_bfloat16 *xs, *ws;
    cudaGetSymbolAddress((void**)&xs, g_xs);
    cudaGetSymbolAddress((void**)&ws, g_ws);

    split3<<<4096, 256>>>(x,    xs, M_TOTAL * C_IN, 0);
    split3<<<1024, 256>>>(wx_w, ws, G4H * C_IN, 1);

    cudaFuncSetAttribute(hmma_pre, cudaFuncAttributeMaxDynamicSharedMemorySize, PRE_SMEM);
    dim3 gridp(G4H / PBM, M_TOTAL / PBN);
    hmma_pre<<<gridp, PTHR, PRE_SMEM>>>(wx_b);

    cudaFuncSetAttribute(lstm_rec, cudaFuncAttributeMaxDynamicSharedMemorySize, REC_SMEM);
    lstm_rec<<<NBLK, NTHR, REC_SMEM>>>(wr_w, wo_w, wc, lengths, (float*)d_out);
}